// round 1
// baseline (speedup 1.0000x reference)
#include <cuda_runtime.h>
#include <cuda_bf16.h>

// Problem constants
namespace cfg {
constexpr int B = 2, S = 2048, D = 1024, H = 16, W = 64;
constexpr int M = B * S;                         // 4096 rows for QKV GEMM
constexpr long long H_ELEMS = (long long)B * S * D;       // 4,194,304
constexpr long long P_ELEMS = (long long)B * H * S * S;   // 134,217,728
}

// Scratch for projected Q, K, V (16 MB each). Device globals: allowed scratch.
__device__ float g_Q[cfg::B * cfg::S * cfg::D];
__device__ float g_K[cfg::B * cfg::S * cfg::D];
__device__ float g_V[cfg::B * cfg::S * cfg::D];

// ---------------------------------------------------------------------------
// Kernel 1: QKV projection. out = x @ W + b for W in {wq, wk, wv} (blockIdx.z)
// M=4096, N=1024, K=1024. 64x64 tile, 16-deep k chunks, 4x4 per thread.
// ---------------------------------------------------------------------------
__global__ __launch_bounds__(256) void qkv_gemm_kernel(
    const float* __restrict__ x,
    const float* __restrict__ wq, const float* __restrict__ bq,
    const float* __restrict__ wk, const float* __restrict__ bk,
    const float* __restrict__ wv, const float* __restrict__ bv)
{
    using namespace cfg;
    const float* w; const float* bias; float* out;
    if (blockIdx.z == 0)      { w = wq; bias = bq; out = g_Q; }
    else if (blockIdx.z == 1) { w = wk; bias = bk; out = g_K; }
    else                      { w = wv; bias = bv; out = g_V; }

    __shared__ float sA[64][17];   // [row][kk], pad 17 vs bank alias
    __shared__ float sB[16][64];   // [kk][col]

    const int tid = threadIdx.x;
    const int tx = tid & 15, ty = tid >> 4;
    const int m0 = blockIdx.y * 64;
    const int n0 = blockIdx.x * 64;

    float acc[4][4] = {};

    for (int k0 = 0; k0 < D; k0 += 16) {
        // Load A tile: 64 rows x 16 k. One float4 per thread.
        {
            const int row = tid >> 2;
            const int kv  = (tid & 3) * 4;
            const float4 v = *reinterpret_cast<const float4*>(
                &x[(size_t)(m0 + row) * D + k0 + kv]);
            sA[row][kv + 0] = v.x; sA[row][kv + 1] = v.y;
            sA[row][kv + 2] = v.z; sA[row][kv + 3] = v.w;
        }
        // Load B tile: 16 k x 64 cols. One float4 per thread, coalesced.
        {
            const int kk = tid >> 4;
            const int c  = (tid & 15) * 4;
            const float4 v = *reinterpret_cast<const float4*>(
                &w[(size_t)(k0 + kk) * D + n0 + c]);
            *reinterpret_cast<float4*>(&sB[kk][c]) = v;
        }
        __syncthreads();
#pragma unroll
        for (int kk = 0; kk < 16; kk++) {
            float a[4], bb[4];
#pragma unroll
            for (int i = 0; i < 4; i++) a[i]  = sA[ty + 16 * i][kk];
#pragma unroll
            for (int j = 0; j < 4; j++) bb[j] = sB[kk][tx + 16 * j];
#pragma unroll
            for (int i = 0; i < 4; i++)
#pragma unroll
                for (int j = 0; j < 4; j++)
                    acc[i][j] = fmaf(a[i], bb[j], acc[i][j]);
        }
        __syncthreads();
    }
#pragma unroll
    for (int i = 0; i < 4; i++) {
        const int r = m0 + ty + 16 * i;
#pragma unroll
        for (int j = 0; j < 4; j++) {
            const int c = n0 + tx + 16 * j;
            out[(size_t)r * D + c] = acc[i][j] + bias[c];
        }
    }
}

// ---------------------------------------------------------------------------
// Kernel 2: raw scores = Q Kt / sqrt(W) - 10000*(1-mask), written to d_out
// scores region. One block = 64(q) x 64(k) tile of one (b,h).
// ---------------------------------------------------------------------------
__global__ __launch_bounds__(256) void scores_kernel(
    const float* __restrict__ mask, float* __restrict__ out_s)
{
    using namespace cfg;
    const int bh = blockIdx.z;            // b*16 + h
    const int b  = bh >> 4, hd = bh & 15;
    const int q0 = blockIdx.y * 64;
    const int k0 = blockIdx.x * 64;

    __shared__ float sQ[64][65];
    __shared__ float sK[64][65];

    const int tid = threadIdx.x;
    const int tx = tid & 15, ty = tid >> 4;

    const float* Qbase = g_Q + (size_t)(b * S + q0) * D + hd * W;
    const float* Kbase = g_K + (size_t)(b * S + k0) * D + hd * W;

#pragma unroll
    for (int u = 0; u < 4; u++) {
        const int idx = tid + 256 * u;
        const int row = idx >> 4;
        const int c   = (idx & 15) * 4;
        const float4 q4 = *reinterpret_cast<const float4*>(&Qbase[(size_t)row * D + c]);
        sQ[row][c + 0] = q4.x; sQ[row][c + 1] = q4.y;
        sQ[row][c + 2] = q4.z; sQ[row][c + 3] = q4.w;
        const float4 k4 = *reinterpret_cast<const float4*>(&Kbase[(size_t)row * D + c]);
        sK[row][c + 0] = k4.x; sK[row][c + 1] = k4.y;
        sK[row][c + 2] = k4.z; sK[row][c + 3] = k4.w;
    }
    __syncthreads();

    float acc[4][4] = {};
#pragma unroll 16
    for (int w = 0; w < 64; w++) {
        float a[4], bb[4];
#pragma unroll
        for (int i = 0; i < 4; i++) a[i]  = sQ[ty + 16 * i][w];
#pragma unroll
        for (int j = 0; j < 4; j++) bb[j] = sK[tx + 16 * j][w];
#pragma unroll
        for (int i = 0; i < 4; i++)
#pragma unroll
            for (int j = 0; j < 4; j++)
                acc[i][j] = fmaf(a[i], bb[j], acc[i][j]);
    }

    const float scale = 0.125f;  // 1/sqrt(64)
    float* dst = out_s + ((size_t)bh * S + q0) * S + k0;
#pragma unroll
    for (int i = 0; i < 4; i++) {
        const int qr = ty + 16 * i;
#pragma unroll
        for (int j = 0; j < 4; j++) {
            const int kr = tx + 16 * j;
            const float mval = mask[b * S + k0 + kr];
            dst[(size_t)qr * S + kr] = acc[i][j] * scale - 10000.0f * (1.0f - mval);
        }
    }
}

// ---------------------------------------------------------------------------
// Kernel 3: row softmax over S=2048. One block per row, 256 threads x 8 elems.
// ---------------------------------------------------------------------------
__global__ __launch_bounds__(256) void softmax_kernel(
    const float* __restrict__ scores, float* __restrict__ soft)
{
    using namespace cfg;
    const long long row = blockIdx.x;               // 0 .. B*H*S-1
    const float* src = scores + row * S;
    float* dst = soft + row * S;
    const int tid  = threadIdx.x;
    const int lane = tid & 31;
    const int wid  = tid >> 5;

    __shared__ float red[8];

    float v[8];
    float m = -1e30f;
#pragma unroll
    for (int u = 0; u < 8; u++) {
        v[u] = src[tid + 256 * u];
        m = fmaxf(m, v[u]);
    }
#pragma unroll
    for (int o = 16; o > 0; o >>= 1) m = fmaxf(m, __shfl_xor_sync(0xffffffffu, m, o));
    if (lane == 0) red[wid] = m;
    __syncthreads();
    float bm = red[0];
#pragma unroll
    for (int i = 1; i < 8; i++) bm = fmaxf(bm, red[i]);
    __syncthreads();

    float s = 0.0f;
#pragma unroll
    for (int u = 0; u < 8; u++) {
        v[u] = __expf(v[u] - bm);
        s += v[u];
    }
#pragma unroll
    for (int o = 16; o > 0; o >>= 1) s += __shfl_xor_sync(0xffffffffu, s, o);
    if (lane == 0) red[wid] = s;
    __syncthreads();
    float tot = 0.0f;
#pragma unroll
    for (int i = 0; i < 8; i++) tot += red[i];
    const float inv = 1.0f / tot;
#pragma unroll
    for (int u = 0; u < 8; u++) dst[tid + 256 * u] = v[u] * inv;
}

// ---------------------------------------------------------------------------
// Kernel 4: h = P @ V per (b,h); writes h into (B,S,D) layout (head-interleaved).
// Block computes 64(q) x 64(W full) tile, k-loop over S in chunks of 64.
// ---------------------------------------------------------------------------
__global__ __launch_bounds__(256) void pv_kernel(
    const float* __restrict__ soft, float* __restrict__ out_h)
{
    using namespace cfg;
    const int bh = blockIdx.z;
    const int b  = bh >> 4, hd = bh & 15;
    const int q0 = blockIdx.y * 64;

    __shared__ float sP[64][65];
    __shared__ float sV[64][65];

    const int tid = threadIdx.x;
    const int tx = tid & 15, ty = tid >> 4;

    const float* Pbase = soft + ((size_t)bh * S + q0) * S;
    const float* Vbase = g_V + (size_t)(b * S) * D + hd * W;

    float acc[4][4] = {};

    for (int k0 = 0; k0 < S; k0 += 64) {
#pragma unroll
        for (int u = 0; u < 4; u++) {
            const int idx = tid + 256 * u;
            const int row = idx >> 4;
            const int c   = (idx & 15) * 4;
            const float4 p4 = *reinterpret_cast<const float4*>(
                &Pbase[(size_t)row * S + k0 + c]);
            sP[row][c + 0] = p4.x; sP[row][c + 1] = p4.y;
            sP[row][c + 2] = p4.z; sP[row][c + 3] = p4.w;
            const float4 v4 = *reinterpret_cast<const float4*>(
                &Vbase[(size_t)(k0 + row) * D + c]);
            sV[row][c + 0] = v4.x; sV[row][c + 1] = v4.y;
            sV[row][c + 2] = v4.z; sV[row][c + 3] = v4.w;
        }
        __syncthreads();
#pragma unroll 16
        for (int kk = 0; kk < 64; kk++) {
            float a[4], bb[4];
#pragma unroll
            for (int i = 0; i < 4; i++) a[i]  = sP[ty + 16 * i][kk];
#pragma unroll
            for (int j = 0; j < 4; j++) bb[j] = sV[kk][tx + 16 * j];
#pragma unroll
            for (int i = 0; i < 4; i++)
#pragma unroll
                for (int j = 0; j < 4; j++)
                    acc[i][j] = fmaf(a[i], bb[j], acc[i][j]);
        }
        __syncthreads();
    }

#pragma unroll
    for (int i = 0; i < 4; i++) {
        const int s = q0 + ty + 16 * i;
#pragma unroll
        for (int j = 0; j < 4; j++) {
            const int wc = tx + 16 * j;
            out_h[(size_t)(b * S + s) * D + hd * W + wc] = acc[i][j];
        }
    }
}

// ---------------------------------------------------------------------------
// Launch. d_out layout (tuple flatten order): [h | scores_soft | scores], fp32.
// ---------------------------------------------------------------------------
extern "C" void kernel_launch(void* const* d_in, const int* in_sizes, int n_in,
                              void* d_out, int out_size)
{
    using namespace cfg;
    (void)in_sizes; (void)n_in; (void)out_size;
    const float* x    = (const float*)d_in[0];
    const float* mask = (const float*)d_in[1];
    const float* wq   = (const float*)d_in[2];
    const float* bq   = (const float*)d_in[3];
    const float* wk   = (const float*)d_in[4];
    const float* bk   = (const float*)d_in[5];
    const float* wv   = (const float*)d_in[6];
    const float* bv   = (const float*)d_in[7];

    float* out   = (float*)d_out;
    float* out_h = out;
    float* out_p = out + H_ELEMS;              // scores_soft
    float* out_s = out + H_ELEMS + P_ELEMS;    // raw scores

    // 1) Q, K, V projections
    {
        dim3 grid(D / 64, M / 64, 3);
        qkv_gemm_kernel<<<grid, 256>>>(x, wq, bq, wk, bk, wv, bv);
    }
    // 2) raw masked/scaled scores
    {
        dim3 grid(S / 64, S / 64, B * H);
        scores_kernel<<<grid, 256>>>(mask, out_s);
    }
    // 3) softmax
    {
        softmax_kernel<<<B * H * S, 256>>>(out_s, out_p);
    }
    // 4) h = P @ V
    {
        dim3 grid(1, S / 64, B * H);
        pv_kernel<<<grid, 256>>>(out_p, out_h);
    }
}

// round 2
// speedup vs baseline: 1.9741x; 1.9741x over previous
#include <cuda_runtime.h>
#include <cuda_bf16.h>
#include <cstdint>

// Problem constants
namespace cfg {
constexpr int B = 2, S = 2048, D = 1024, H = 16, W = 64;
constexpr int M = B * S;                                  // 4096
constexpr long long H_ELEMS = (long long)B * S * D;       // 4,194,304
constexpr long long P_ELEMS = (long long)B * H * S * S;   // 134,217,728
}

// Scratch for projected Q, K, V (16 MB each).
__device__ float g_Q[cfg::B * cfg::S * cfg::D];
__device__ float g_K[cfg::B * cfg::S * cfg::D];
__device__ float g_V[cfg::B * cfg::S * cfg::D];

// ---------------------------------------------------------------------------
// Helpers: split-bf16 (hi+lo) packing and bf16 mma.sync
// ---------------------------------------------------------------------------
__device__ __forceinline__ void splitpair(float x0, float x1,
                                          uint32_t& hi, uint32_t& lo)
{
    __nv_bfloat16 h0 = __float2bfloat16(x0);
    __nv_bfloat16 h1 = __float2bfloat16(x1);
    __nv_bfloat16 l0 = __float2bfloat16(x0 - __bfloat162float(h0));
    __nv_bfloat16 l1 = __float2bfloat16(x1 - __bfloat162float(h1));
    hi = ((uint32_t)__bfloat16_as_ushort(h1) << 16) | __bfloat16_as_ushort(h0);
    lo = ((uint32_t)__bfloat16_as_ushort(l1) << 16) | __bfloat16_as_ushort(l0);
}

__device__ __forceinline__ void bmma(float& d0, float& d1, float& d2, float& d3,
                                     uint32_t a0, uint32_t a1, uint32_t a2, uint32_t a3,
                                     uint32_t b0, uint32_t b1)
{
    asm volatile(
        "mma.sync.aligned.m16n8k16.row.col.f32.bf16.bf16.f32 "
        "{%0,%1,%2,%3},{%4,%5,%6,%7},{%8,%9},{%0,%1,%2,%3};\n"
        : "+f"(d0), "+f"(d1), "+f"(d2), "+f"(d3)
        : "r"(a0), "r"(a1), "r"(a2), "r"(a3), "r"(b0), "r"(b1));
}

// ---------------------------------------------------------------------------
// Kernel 1: QKV projection. out = x @ W + b, z selects Q/K/V.
// Tile 128x128, BK=32. 8 warps = 2(m) x 4(n); warp tile 64x32.
// ---------------------------------------------------------------------------
__global__ __launch_bounds__(256) void qkv_gemm_kernel(
    const float* __restrict__ x,
    const float* __restrict__ wq, const float* __restrict__ bq,
    const float* __restrict__ wk, const float* __restrict__ bk,
    const float* __restrict__ wv, const float* __restrict__ bv)
{
    using namespace cfg;
    const float* w; const float* bias; float* out;
    if (blockIdx.z == 0)      { w = wq; bias = bq; out = g_Q; }
    else if (blockIdx.z == 1) { w = wk; bias = bk; out = g_K; }
    else                      { w = wv; bias = bv; out = g_V; }

    // stride 20 u32 (16 + 4 pad): conflict-free fragment loads
    __shared__ __align__(16) uint32_t sAh[128][20], sAl[128][20];
    __shared__ __align__(16) uint32_t sBh[128][20], sBl[128][20];  // [n][k2]

    const int tid = threadIdx.x;
    const int lane = tid & 31, wid = tid >> 5;
    const int g = lane >> 2, t = lane & 3;
    const int wm = wid & 1, wn = wid >> 1;
    const int m0 = blockIdx.y * 128;
    const int n0 = blockIdx.x * 128;

    float acc[4][4][4] = {};

    for (int k0 = 0; k0 < D; k0 += 32) {
        // A tile: 128 rows x 32 k, pairs along k
#pragma unroll
        for (int p = 0; p < 4; p++) {
            int idx = tid + 256 * p;
            int row = idx >> 3;
            int c4  = (idx & 7) * 4;
            const float4 v = *reinterpret_cast<const float4*>(
                &x[(size_t)(m0 + row) * D + k0 + c4]);
            uint32_t h0, l0, h1, l1;
            splitpair(v.x, v.y, h0, l0);
            splitpair(v.z, v.w, h1, l1);
            *reinterpret_cast<uint2*>(&sAh[row][c4 >> 1]) = make_uint2(h0, h1);
            *reinterpret_cast<uint2*>(&sAl[row][c4 >> 1]) = make_uint2(l0, l1);
        }
        // B tile transposed: sB[n][k2] with k-pairs gathered from 2 rows
#pragma unroll
        for (int p = 0; p < 8; p++) {
            int e  = tid + 256 * p;
            int n  = e & 127;
            int k2 = e >> 7;
            const float v0 = w[(size_t)(k0 + 2 * k2)     * D + n0 + n];
            const float v1 = w[(size_t)(k0 + 2 * k2 + 1) * D + n0 + n];
            uint32_t h, l;
            splitpair(v0, v1, h, l);
            sBh[n][k2] = h;
            sBl[n][k2] = l;
        }
        __syncthreads();

#pragma unroll
        for (int ka = 0; ka < 2; ka++) {
            uint32_t bh[4][2], bl[4][2];
#pragma unroll
            for (int na = 0; na < 4; na++) {
                int n = wn * 32 + na * 8 + g;
                bh[na][0] = sBh[n][ka * 8 + t];
                bh[na][1] = sBh[n][ka * 8 + t + 4];
                bl[na][0] = sBl[n][ka * 8 + t];
                bl[na][1] = sBl[n][ka * 8 + t + 4];
            }
#pragma unroll
            for (int ma = 0; ma < 4; ma++) {
                int r = wm * 64 + ma * 16 + g;
                int c = ka * 8 + t;
                uint32_t ah0 = sAh[r][c],     ah1 = sAh[r + 8][c];
                uint32_t ah2 = sAh[r][c + 4], ah3 = sAh[r + 8][c + 4];
                uint32_t al0 = sAl[r][c],     al1 = sAl[r + 8][c];
                uint32_t al2 = sAl[r][c + 4], al3 = sAl[r + 8][c + 4];
#pragma unroll
                for (int na = 0; na < 4; na++) {
                    float* d = acc[ma][na];
                    bmma(d[0], d[1], d[2], d[3], ah0, ah1, ah2, ah3, bh[na][0], bh[na][1]);
                    bmma(d[0], d[1], d[2], d[3], ah0, ah1, ah2, ah3, bl[na][0], bl[na][1]);
                    bmma(d[0], d[1], d[2], d[3], al0, al1, al2, al3, bh[na][0], bh[na][1]);
                }
            }
        }
        __syncthreads();
    }

#pragma unroll
    for (int ma = 0; ma < 4; ma++) {
#pragma unroll
        for (int na = 0; na < 4; na++) {
            int row = m0 + wm * 64 + ma * 16 + g;
            int col = n0 + wn * 32 + na * 8 + 2 * t;
            float b0 = bias[col], b1 = bias[col + 1];
            float* d = acc[ma][na];
            *reinterpret_cast<float2*>(&out[(size_t)row * D + col]) =
                make_float2(d[0] + b0, d[1] + b1);
            *reinterpret_cast<float2*>(&out[(size_t)(row + 8) * D + col]) =
                make_float2(d[2] + b0, d[3] + b1);
        }
    }
}

// ---------------------------------------------------------------------------
// Kernel 2: scores = Q Kt / 8 - 10000*(1-mask). Tile 128(q) x 128(k), K=64
// in two 32-chunks. Both operands natural k-pair layout (k = head width).
// ---------------------------------------------------------------------------
__global__ __launch_bounds__(256) void scores_kernel(
    const float* __restrict__ mask, float* __restrict__ out_s)
{
    using namespace cfg;
    const int bh = blockIdx.z;
    const int b  = bh >> 4, hd = bh & 15;
    const int q0 = blockIdx.y * 128;
    const int k0 = blockIdx.x * 128;

    __shared__ __align__(16) uint32_t sQh[128][20], sQl[128][20];
    __shared__ __align__(16) uint32_t sKh[128][20], sKl[128][20];  // [kpos][w2]

    const int tid = threadIdx.x;
    const int lane = tid & 31, wid = tid >> 5;
    const int g = lane >> 2, t = lane & 3;
    const int wm = wid & 1, wn = wid >> 1;

    const float* Qbase = g_Q + (size_t)(b * S + q0) * D + hd * W;
    const float* Kbase = g_K + (size_t)(b * S + k0) * D + hd * W;

    float acc[4][4][4] = {};

    for (int ch = 0; ch < 2; ch++) {
        const int w0 = ch * 32;
#pragma unroll
        for (int p = 0; p < 4; p++) {
            int idx = tid + 256 * p;
            int row = idx >> 3;
            int c4  = (idx & 7) * 4;
            const float4 q4 = *reinterpret_cast<const float4*>(
                &Qbase[(size_t)row * D + w0 + c4]);
            uint32_t h0, l0, h1, l1;
            splitpair(q4.x, q4.y, h0, l0);
            splitpair(q4.z, q4.w, h1, l1);
            *reinterpret_cast<uint2*>(&sQh[row][c4 >> 1]) = make_uint2(h0, h1);
            *reinterpret_cast<uint2*>(&sQl[row][c4 >> 1]) = make_uint2(l0, l1);
            const float4 k4 = *reinterpret_cast<const float4*>(
                &Kbase[(size_t)row * D + w0 + c4]);
            splitpair(k4.x, k4.y, h0, l0);
            splitpair(k4.z, k4.w, h1, l1);
            *reinterpret_cast<uint2*>(&sKh[row][c4 >> 1]) = make_uint2(h0, h1);
            *reinterpret_cast<uint2*>(&sKl[row][c4 >> 1]) = make_uint2(l0, l1);
        }
        __syncthreads();

#pragma unroll
        for (int ka = 0; ka < 2; ka++) {
            uint32_t bh_[4][2], bl_[4][2];
#pragma unroll
            for (int na = 0; na < 4; na++) {
                int n = wn * 32 + na * 8 + g;
                bh_[na][0] = sKh[n][ka * 8 + t];
                bh_[na][1] = sKh[n][ka * 8 + t + 4];
                bl_[na][0] = sKl[n][ka * 8 + t];
                bl_[na][1] = sKl[n][ka * 8 + t + 4];
            }
#pragma unroll
            for (int ma = 0; ma < 4; ma++) {
                int r = wm * 64 + ma * 16 + g;
                int c = ka * 8 + t;
                uint32_t ah0 = sQh[r][c],     ah1 = sQh[r + 8][c];
                uint32_t ah2 = sQh[r][c + 4], ah3 = sQh[r + 8][c + 4];
                uint32_t al0 = sQl[r][c],     al1 = sQl[r + 8][c];
                uint32_t al2 = sQl[r][c + 4], al3 = sQl[r + 8][c + 4];
#pragma unroll
                for (int na = 0; na < 4; na++) {
                    float* d = acc[ma][na];
                    bmma(d[0], d[1], d[2], d[3], ah0, ah1, ah2, ah3, bh_[na][0], bh_[na][1]);
                    bmma(d[0], d[1], d[2], d[3], ah0, ah1, ah2, ah3, bl_[na][0], bl_[na][1]);
                    bmma(d[0], d[1], d[2], d[3], al0, al1, al2, al3, bh_[na][0], bh_[na][1]);
                }
            }
        }
        __syncthreads();
    }

    const float scale = 0.125f;
    float* dst = out_s + ((size_t)bh * S + q0) * S + k0;
#pragma unroll
    for (int ma = 0; ma < 4; ma++) {
#pragma unroll
        for (int na = 0; na < 4; na++) {
            int rowl = wm * 64 + ma * 16 + g;
            int coll = wn * 32 + na * 8 + 2 * t;
            float m0v = mask[b * S + k0 + coll];
            float m1v = mask[b * S + k0 + coll + 1];
            float a0 = -10000.0f * (1.0f - m0v);
            float a1 = -10000.0f * (1.0f - m1v);
            float* d = acc[ma][na];
            *reinterpret_cast<float2*>(&dst[(size_t)rowl * S + coll]) =
                make_float2(d[0] * scale + a0, d[1] * scale + a1);
            *reinterpret_cast<float2*>(&dst[(size_t)(rowl + 8) * S + coll]) =
                make_float2(d[2] * scale + a0, d[3] * scale + a1);
        }
    }
}

// ---------------------------------------------------------------------------
// Kernel 3: row softmax over S=2048. One block per row.
// ---------------------------------------------------------------------------
__global__ __launch_bounds__(256) void softmax_kernel(
    const float* __restrict__ scores, float* __restrict__ soft)
{
    using namespace cfg;
    const long long row = blockIdx.x;
    const float* src = scores + row * S;
    float* dst = soft + row * S;
    const int tid  = threadIdx.x;
    const int lane = tid & 31;
    const int wid  = tid >> 5;

    __shared__ float red[8];

    float v[8];
    float m = -1e30f;
#pragma unroll
    for (int u = 0; u < 8; u++) {
        v[u] = src[tid + 256 * u];
        m = fmaxf(m, v[u]);
    }
#pragma unroll
    for (int o = 16; o > 0; o >>= 1) m = fmaxf(m, __shfl_xor_sync(0xffffffffu, m, o));
    if (lane == 0) red[wid] = m;
    __syncthreads();
    float bm = red[0];
#pragma unroll
    for (int i = 1; i < 8; i++) bm = fmaxf(bm, red[i]);
    __syncthreads();

    float s = 0.0f;
#pragma unroll
    for (int u = 0; u < 8; u++) {
        v[u] = __expf(v[u] - bm);
        s += v[u];
    }
#pragma unroll
    for (int o = 16; o > 0; o >>= 1) s += __shfl_xor_sync(0xffffffffu, s, o);
    if (lane == 0) red[wid] = s;
    __syncthreads();
    float tot = 0.0f;
#pragma unroll
    for (int i = 0; i < 8; i++) tot += red[i];
    const float inv = 1.0f / tot;
#pragma unroll
    for (int u = 0; u < 8; u++) dst[tid + 256 * u] = v[u] * inv;
}

// ---------------------------------------------------------------------------
// Kernel 4: h = P @ V. Tile 128(q) x 64(w), BK=32 over kpos.
// 8 warps = 4(m) x 2(n); warp tile 32x32. V transposed to [w][k2] in smem.
// ---------------------------------------------------------------------------
__global__ __launch_bounds__(256) void pv_kernel(
    const float* __restrict__ soft, float* __restrict__ out_h)
{
    using namespace cfg;
    const int bh = blockIdx.y;
    const int b  = bh >> 4, hd = bh & 15;
    const int q0 = blockIdx.x * 128;

    __shared__ __align__(16) uint32_t sPh[128][20], sPl[128][20];
    __shared__ __align__(16) uint32_t sVh[64][20],  sVl[64][20];   // [w][k2]

    const int tid = threadIdx.x;
    const int lane = tid & 31, wid = tid >> 5;
    const int g = lane >> 2, t = lane & 3;
    const int wm = wid & 3, wn = wid >> 2;

    const float* Pbase = soft + ((size_t)bh * S + q0) * S;
    const float* Vbase = g_V + (size_t)(b * S) * D + hd * W;

    float acc[2][4][4] = {};

    for (int k0 = 0; k0 < S; k0 += 32) {
        // P tile: 128 q-rows x 32 kpos, pairs along kpos (natural)
#pragma unroll
        for (int p = 0; p < 4; p++) {
            int idx = tid + 256 * p;
            int row = idx >> 3;
            int c4  = (idx & 7) * 4;
            const float4 v = *reinterpret_cast<const float4*>(
                &Pbase[(size_t)row * S + k0 + c4]);
            uint32_t h0, l0, h1, l1;
            splitpair(v.x, v.y, h0, l0);
            splitpair(v.z, v.w, h1, l1);
            *reinterpret_cast<uint2*>(&sPh[row][c4 >> 1]) = make_uint2(h0, h1);
            *reinterpret_cast<uint2*>(&sPl[row][c4 >> 1]) = make_uint2(l0, l1);
        }
        // V tile transposed: sV[w][k2], pairs gathered from 2 kpos rows
#pragma unroll
        for (int p = 0; p < 4; p++) {
            int e  = tid + 256 * p;
            int wcol = e & 63;
            int k2 = e >> 6;          // 0..15
            const float v0 = Vbase[(size_t)(k0 + 2 * k2)     * D + wcol];
            const float v1 = Vbase[(size_t)(k0 + 2 * k2 + 1) * D + wcol];
            uint32_t h, l;
            splitpair(v0, v1, h, l);
            sVh[wcol][k2] = h;
            sVl[wcol][k2] = l;
        }
        __syncthreads();

#pragma unroll
        for (int ka = 0; ka < 2; ka++) {
            uint32_t bh_[4][2], bl_[4][2];
#pragma unroll
            for (int na = 0; na < 4; na++) {
                int n = wn * 32 + na * 8 + g;
                bh_[na][0] = sVh[n][ka * 8 + t];
                bh_[na][1] = sVh[n][ka * 8 + t + 4];
                bl_[na][0] = sVl[n][ka * 8 + t];
                bl_[na][1] = sVl[n][ka * 8 + t + 4];
            }
#pragma unroll
            for (int ma = 0; ma < 2; ma++) {
                int r = wm * 32 + ma * 16 + g;
                int c = ka * 8 + t;
                uint32_t ah0 = sPh[r][c],     ah1 = sPh[r + 8][c];
                uint32_t ah2 = sPh[r][c + 4], ah3 = sPh[r + 8][c + 4];
                uint32_t al0 = sPl[r][c],     al1 = sPl[r + 8][c];
                uint32_t al2 = sPl[r][c + 4], al3 = sPl[r + 8][c + 4];
#pragma unroll
                for (int na = 0; na < 4; na++) {
                    float* d = acc[ma][na];
                    bmma(d[0], d[1], d[2], d[3], ah0, ah1, ah2, ah3, bh_[na][0], bh_[na][1]);
                    bmma(d[0], d[1], d[2], d[3], ah0, ah1, ah2, ah3, bl_[na][0], bl_[na][1]);
                    bmma(d[0], d[1], d[2], d[3], al0, al1, al2, al3, bh_[na][0], bh_[na][1]);
                }
            }
        }
        __syncthreads();
    }

#pragma unroll
    for (int ma = 0; ma < 2; ma++) {
#pragma unroll
        for (int na = 0; na < 4; na++) {
            int rowl = wm * 32 + ma * 16 + g;
            int coll = wn * 32 + na * 8 + 2 * t;
            float* d = acc[ma][na];
            size_t base = (size_t)(b * S + q0 + rowl) * D + hd * W + coll;
            *reinterpret_cast<float2*>(&out_h[base]) = make_float2(d[0], d[1]);
            *reinterpret_cast<float2*>(&out_h[base + (size_t)8 * D]) = make_float2(d[2], d[3]);
        }
    }
}

// ---------------------------------------------------------------------------
// Launch. d_out layout: [h | scores_soft | scores], fp32.
// ---------------------------------------------------------------------------
extern "C" void kernel_launch(void* const* d_in, const int* in_sizes, int n_in,
                              void* d_out, int out_size)
{
    using namespace cfg;
    (void)in_sizes; (void)n_in; (void)out_size;
    const float* x    = (const float*)d_in[0];
    const float* mask = (const float*)d_in[1];
    const float* wq   = (const float*)d_in[2];
    const float* bq   = (const float*)d_in[3];
    const float* wk   = (const float*)d_in[4];
    const float* bk   = (const float*)d_in[5];
    const float* wv   = (const float*)d_in[6];
    const float* bv   = (const float*)d_in[7];

    float* out   = (float*)d_out;
    float* out_h = out;
    float* out_p = out + H_ELEMS;              // scores_soft
    float* out_s = out + H_ELEMS + P_ELEMS;    // raw scores

    {
        dim3 grid(D / 128, M / 128, 3);
        qkv_gemm_kernel<<<grid, 256>>>(x, wq, bq, wk, bk, wv, bv);
    }
    {
        dim3 grid(S / 128, S / 128, B * H);
        scores_kernel<<<grid, 256>>>(mask, out_s);
    }
    {
        softmax_kernel<<<B * H * S, 256>>>(out_s, out_p);
    }
    {
        dim3 grid(S / 128, B * H);
        pv_kernel<<<grid, 256>>>(out_p, out_h);
    }
}

// round 4
// speedup vs baseline: 1.9789x; 1.0024x over previous
#include <cuda_runtime.h>
#include <cuda_bf16.h>
#include <cstdint>

// Problem constants
namespace cfg {
constexpr int B = 2, S = 2048, D = 1024, H = 16, W = 64;
constexpr int M = B * S;                                  // 4096
constexpr int ROWS = B * H * S;                           // 65536 score rows
constexpr int KT = S / 128;                               // 16 k-tiles per row
constexpr long long H_ELEMS = (long long)B * S * D;       // 4,194,304
constexpr long long P_ELEMS = (long long)B * H * S * S;   // 134,217,728
}

// Scratch: projected Q/K/V (16 MB each), softmax partials + stats.
__device__ float g_Q[cfg::B * cfg::S * cfg::D];
__device__ float g_K[cfg::B * cfg::S * cfg::D];
__device__ float g_V[cfg::B * cfg::S * cfg::D];
__device__ float2 g_part[cfg::ROWS * cfg::KT];   // per (row, ktile): (max, sumexp)
__device__ float2 g_stats[cfg::ROWS];            // per row: (max, 1/sum)

// ---------------------------------------------------------------------------
// Helpers: split-bf16 (hi+lo) packing and bf16 mma.sync
// ---------------------------------------------------------------------------
__device__ __forceinline__ void splitpair(float x0, float x1,
                                          uint32_t& hi, uint32_t& lo)
{
    __nv_bfloat16 h0 = __float2bfloat16(x0);
    __nv_bfloat16 h1 = __float2bfloat16(x1);
    __nv_bfloat16 l0 = __float2bfloat16(x0 - __bfloat162float(h0));
    __nv_bfloat16 l1 = __float2bfloat16(x1 - __bfloat162float(h1));
    hi = ((uint32_t)__bfloat16_as_ushort(h1) << 16) | __bfloat16_as_ushort(h0);
    lo = ((uint32_t)__bfloat16_as_ushort(l1) << 16) | __bfloat16_as_ushort(l0);
}

__device__ __forceinline__ void bmma(float& d0, float& d1, float& d2, float& d3,
                                     uint32_t a0, uint32_t a1, uint32_t a2, uint32_t a3,
                                     uint32_t b0, uint32_t b1)
{
    asm volatile(
        "mma.sync.aligned.m16n8k16.row.col.f32.bf16.bf16.f32 "
        "{%0,%1,%2,%3},{%4,%5,%6,%7},{%8,%9},{%0,%1,%2,%3};\n"
        : "+f"(d0), "+f"(d1), "+f"(d2), "+f"(d3)
        : "r"(a0), "r"(a1), "r"(a2), "r"(a3), "r"(b0), "r"(b1));
}

// ---------------------------------------------------------------------------
// Kernel 1: QKV projection. out = x @ W + b, z selects Q/K/V.
// Tile 128x128, BK=32. 8 warps = 2(m) x 4(n); warp tile 64x32.
// ---------------------------------------------------------------------------
__global__ __launch_bounds__(256) void qkv_gemm_kernel(
    const float* __restrict__ x,
    const float* __restrict__ wq, const float* __restrict__ bq,
    const float* __restrict__ wk, const float* __restrict__ bk,
    const float* __restrict__ wv, const float* __restrict__ bv)
{
    using namespace cfg;
    const float* w; const float* bias; float* out;
    if (blockIdx.z == 0)      { w = wq; bias = bq; out = g_Q; }
    else if (blockIdx.z == 1) { w = wk; bias = bk; out = g_K; }
    else                      { w = wv; bias = bv; out = g_V; }

    __shared__ __align__(16) uint32_t sAh[128][20], sAl[128][20];
    __shared__ __align__(16) uint32_t sBh[128][20], sBl[128][20];  // [n][k2]

    const int tid = threadIdx.x;
    const int lane = tid & 31, wid = tid >> 5;
    const int g = lane >> 2, t = lane & 3;
    const int wm = wid & 1, wn = wid >> 1;
    const int m0 = blockIdx.y * 128;
    const int n0 = blockIdx.x * 128;

    float acc[4][4][4] = {};

    for (int k0 = 0; k0 < D; k0 += 32) {
#pragma unroll
        for (int p = 0; p < 4; p++) {
            int idx = tid + 256 * p;
            int row = idx >> 3;
            int c4  = (idx & 7) * 4;
            const float4 v = *reinterpret_cast<const float4*>(
                &x[(size_t)(m0 + row) * D + k0 + c4]);
            uint32_t h0, l0, h1, l1;
            splitpair(v.x, v.y, h0, l0);
            splitpair(v.z, v.w, h1, l1);
            *reinterpret_cast<uint2*>(&sAh[row][c4 >> 1]) = make_uint2(h0, h1);
            *reinterpret_cast<uint2*>(&sAl[row][c4 >> 1]) = make_uint2(l0, l1);
        }
#pragma unroll
        for (int p = 0; p < 8; p++) {
            int e  = tid + 256 * p;
            int n  = e & 127;
            int k2 = e >> 7;
            const float v0 = w[(size_t)(k0 + 2 * k2)     * D + n0 + n];
            const float v1 = w[(size_t)(k0 + 2 * k2 + 1) * D + n0 + n];
            uint32_t h, l;
            splitpair(v0, v1, h, l);
            sBh[n][k2] = h;
            sBl[n][k2] = l;
        }
        __syncthreads();

#pragma unroll
        for (int ka = 0; ka < 2; ka++) {
            uint32_t bh[4][2], bl[4][2];
#pragma unroll
            for (int na = 0; na < 4; na++) {
                int n = wn * 32 + na * 8 + g;
                bh[na][0] = sBh[n][ka * 8 + t];
                bh[na][1] = sBh[n][ka * 8 + t + 4];
                bl[na][0] = sBl[n][ka * 8 + t];
                bl[na][1] = sBl[n][ka * 8 + t + 4];
            }
#pragma unroll
            for (int ma = 0; ma < 4; ma++) {
                int r = wm * 64 + ma * 16 + g;
                int c = ka * 8 + t;
                uint32_t ah0 = sAh[r][c],     ah1 = sAh[r + 8][c];
                uint32_t ah2 = sAh[r][c + 4], ah3 = sAh[r + 8][c + 4];
                uint32_t al0 = sAl[r][c],     al1 = sAl[r + 8][c];
                uint32_t al2 = sAl[r][c + 4], al3 = sAl[r + 8][c + 4];
#pragma unroll
                for (int na = 0; na < 4; na++) {
                    float* d = acc[ma][na];
                    bmma(d[0], d[1], d[2], d[3], ah0, ah1, ah2, ah3, bh[na][0], bh[na][1]);
                    bmma(d[0], d[1], d[2], d[3], ah0, ah1, ah2, ah3, bl[na][0], bl[na][1]);
                    bmma(d[0], d[1], d[2], d[3], al0, al1, al2, al3, bh[na][0], bh[na][1]);
                }
            }
        }
        __syncthreads();
    }

#pragma unroll
    for (int ma = 0; ma < 4; ma++) {
#pragma unroll
        for (int na = 0; na < 4; na++) {
            int row = m0 + wm * 64 + ma * 16 + g;
            int col = n0 + wn * 32 + na * 8 + 2 * t;
            float b0 = bias[col], b1 = bias[col + 1];
            float* d = acc[ma][na];
            *reinterpret_cast<float2*>(&out[(size_t)row * D + col]) =
                make_float2(d[0] + b0, d[1] + b1);
            *reinterpret_cast<float2*>(&out[(size_t)(row + 8) * D + col]) =
                make_float2(d[2] + b0, d[3] + b1);
        }
    }
}

// ---------------------------------------------------------------------------
// Kernel 2: scores = Q Kt / 8 - 10000*(1-mask), plus per-(row, 128-tile)
// softmax partials (max, sumexp). Tile 128(q) x 128(k).
// ---------------------------------------------------------------------------
__global__ __launch_bounds__(256) void scores_kernel(
    const float* __restrict__ mask, float* __restrict__ out_s)
{
    using namespace cfg;
    const int bh = blockIdx.z;
    const int b  = bh >> 4, hd = bh & 15;
    const int q0 = blockIdx.y * 128;
    const int k0 = blockIdx.x * 128;

    __shared__ __align__(16) uint32_t sQh[128][20], sQl[128][20];
    __shared__ __align__(16) uint32_t sKh[128][20], sKl[128][20];
    __shared__ float redM[128][4];
    __shared__ float redS[128][4];

    const int tid = threadIdx.x;
    const int lane = tid & 31, wid = tid >> 5;
    const int g = lane >> 2, t = lane & 3;
    const int wm = wid & 1, wn = wid >> 1;

    const float* Qbase = g_Q + (size_t)(b * S + q0) * D + hd * W;
    const float* Kbase = g_K + (size_t)(b * S + k0) * D + hd * W;

    float acc[4][4][4] = {};

    for (int ch = 0; ch < 2; ch++) {
        const int w0 = ch * 32;
#pragma unroll
        for (int p = 0; p < 4; p++) {
            int idx = tid + 256 * p;
            int row = idx >> 3;
            int c4  = (idx & 7) * 4;
            const float4 q4 = *reinterpret_cast<const float4*>(
                &Qbase[(size_t)row * D + w0 + c4]);
            uint32_t h0, l0, h1, l1;
            splitpair(q4.x, q4.y, h0, l0);
            splitpair(q4.z, q4.w, h1, l1);
            *reinterpret_cast<uint2*>(&sQh[row][c4 >> 1]) = make_uint2(h0, h1);
            *reinterpret_cast<uint2*>(&sQl[row][c4 >> 1]) = make_uint2(l0, l1);
            const float4 k4 = *reinterpret_cast<const float4*>(
                &Kbase[(size_t)row * D + w0 + c4]);
            splitpair(k4.x, k4.y, h0, l0);
            splitpair(k4.z, k4.w, h1, l1);
            *reinterpret_cast<uint2*>(&sKh[row][c4 >> 1]) = make_uint2(h0, h1);
            *reinterpret_cast<uint2*>(&sKl[row][c4 >> 1]) = make_uint2(l0, l1);
        }
        __syncthreads();

#pragma unroll
        for (int ka = 0; ka < 2; ka++) {
            uint32_t bh_[4][2], bl_[4][2];
#pragma unroll
            for (int na = 0; na < 4; na++) {
                int n = wn * 32 + na * 8 + g;
                bh_[na][0] = sKh[n][ka * 8 + t];
                bh_[na][1] = sKh[n][ka * 8 + t + 4];
                bl_[na][0] = sKl[n][ka * 8 + t];
                bl_[na][1] = sKl[n][ka * 8 + t + 4];
            }
#pragma unroll
            for (int ma = 0; ma < 4; ma++) {
                int r = wm * 64 + ma * 16 + g;
                int c = ka * 8 + t;
                uint32_t ah0 = sQh[r][c],     ah1 = sQh[r + 8][c];
                uint32_t ah2 = sQh[r][c + 4], ah3 = sQh[r + 8][c + 4];
                uint32_t al0 = sQl[r][c],     al1 = sQl[r + 8][c];
                uint32_t al2 = sQl[r][c + 4], al3 = sQl[r + 8][c + 4];
#pragma unroll
                for (int na = 0; na < 4; na++) {
                    float* d = acc[ma][na];
                    bmma(d[0], d[1], d[2], d[3], ah0, ah1, ah2, ah3, bh_[na][0], bh_[na][1]);
                    bmma(d[0], d[1], d[2], d[3], ah0, ah1, ah2, ah3, bl_[na][0], bl_[na][1]);
                    bmma(d[0], d[1], d[2], d[3], al0, al1, al2, al3, bh_[na][0], bh_[na][1]);
                }
            }
        }
        __syncthreads();
    }

    // Scale + mask, store scores, keep values in acc, track per-row-half max.
    const float scale = 0.125f;
    float* dst = out_s + ((size_t)bh * S + q0) * S + k0;
    float rmax[4][2];
#pragma unroll
    for (int ma = 0; ma < 4; ma++) { rmax[ma][0] = -1e30f; rmax[ma][1] = -1e30f; }

#pragma unroll
    for (int ma = 0; ma < 4; ma++) {
#pragma unroll
        for (int na = 0; na < 4; na++) {
            int rowl = wm * 64 + ma * 16 + g;
            int coll = wn * 32 + na * 8 + 2 * t;
            float m0v = mask[b * S + k0 + coll];
            float m1v = mask[b * S + k0 + coll + 1];
            float a0 = -10000.0f * (1.0f - m0v);
            float a1 = -10000.0f * (1.0f - m1v);
            float* d = acc[ma][na];
            float v0 = d[0] * scale + a0, v1 = d[1] * scale + a1;
            float v2 = d[2] * scale + a0, v3 = d[3] * scale + a1;
            d[0] = v0; d[1] = v1; d[2] = v2; d[3] = v3;
            *reinterpret_cast<float2*>(&dst[(size_t)rowl * S + coll]) = make_float2(v0, v1);
            *reinterpret_cast<float2*>(&dst[(size_t)(rowl + 8) * S + coll]) = make_float2(v2, v3);
            rmax[ma][0] = fmaxf(rmax[ma][0], fmaxf(v0, v1));
            rmax[ma][1] = fmaxf(rmax[ma][1], fmaxf(v2, v3));
        }
    }
    // reduce max over t (lanes differing in bits 0-1)
#pragma unroll
    for (int ma = 0; ma < 4; ma++)
#pragma unroll
        for (int hf = 0; hf < 2; hf++) {
            float m = rmax[ma][hf];
            m = fmaxf(m, __shfl_xor_sync(0xffffffffu, m, 1));
            m = fmaxf(m, __shfl_xor_sync(0xffffffffu, m, 2));
            rmax[ma][hf] = m;
        }
    if (t == 0) {
#pragma unroll
        for (int ma = 0; ma < 4; ma++)
#pragma unroll
            for (int hf = 0; hf < 2; hf++)
                redM[wm * 64 + ma * 16 + g + hf * 8][wn] = rmax[ma][hf];
    }
    __syncthreads();

    // final max per row (for this tile), local sumexp
    float se[4][2];
#pragma unroll
    for (int ma = 0; ma < 4; ma++)
#pragma unroll
        for (int hf = 0; hf < 2; hf++) {
            int row = wm * 64 + ma * 16 + g + hf * 8;
            float m = fmaxf(fmaxf(redM[row][0], redM[row][1]),
                            fmaxf(redM[row][2], redM[row][3]));
            rmax[ma][hf] = m;
            se[ma][hf] = 0.0f;
        }
#pragma unroll
    for (int ma = 0; ma < 4; ma++)
#pragma unroll
        for (int na = 0; na < 4; na++) {
            float* d = acc[ma][na];
            se[ma][0] += __expf(d[0] - rmax[ma][0]) + __expf(d[1] - rmax[ma][0]);
            se[ma][1] += __expf(d[2] - rmax[ma][1]) + __expf(d[3] - rmax[ma][1]);
        }
#pragma unroll
    for (int ma = 0; ma < 4; ma++)
#pragma unroll
        for (int hf = 0; hf < 2; hf++) {
            float s = se[ma][hf];
            s += __shfl_xor_sync(0xffffffffu, s, 1);
            s += __shfl_xor_sync(0xffffffffu, s, 2);
            se[ma][hf] = s;
        }
    if (t == 0) {
#pragma unroll
        for (int ma = 0; ma < 4; ma++)
#pragma unroll
            for (int hf = 0; hf < 2; hf++)
                redS[wm * 64 + ma * 16 + g + hf * 8][wn] = se[ma][hf];
    }
    __syncthreads();

    if (tid < 128) {
        int row = tid;
        float m = fmaxf(fmaxf(redM[row][0], redM[row][1]),
                        fmaxf(redM[row][2], redM[row][3]));
        float s = redS[row][0] + redS[row][1] + redS[row][2] + redS[row][3];
        g_part[((size_t)bh * S + q0 + row) * KT + blockIdx.x] = make_float2(m, s);
    }
}

// ---------------------------------------------------------------------------
// Kernel 3: combine per-row tile partials -> (max, 1/sum)
// ---------------------------------------------------------------------------
__global__ __launch_bounds__(256) void combine_kernel()
{
    using namespace cfg;
    int row = blockIdx.x * 256 + threadIdx.x;
    const float2* p = &g_part[(size_t)row * KT];
    float m = -1e30f;
#pragma unroll
    for (int i = 0; i < KT; i++) m = fmaxf(m, p[i].x);
    float s = 0.0f;
#pragma unroll
    for (int i = 0; i < KT; i++) s += p[i].y * __expf(p[i].x - m);
    g_stats[row] = make_float2(m, 1.0f / s);
}

// ---------------------------------------------------------------------------
// Kernel 4: fused softmax-apply + P@V. Reads raw scores, writes soft, writes h.
// Tile 128(q) x 64(w), BK=32; register-prefetch pipeline over k chunks.
// ---------------------------------------------------------------------------
__global__ __launch_bounds__(256, 2) void pv_kernel(
    const float* __restrict__ scores, float* __restrict__ soft,
    float* __restrict__ out_h)
{
    using namespace cfg;
    const int bh = blockIdx.y;
    const int b  = bh >> 4, hd = bh & 15;
    const int q0 = blockIdx.x * 128;

    __shared__ __align__(16) uint32_t sPh[128][20], sPl[128][20];
    __shared__ __align__(16) uint32_t sVh[64][20],  sVl[64][20];
    __shared__ float2 sStats[128];

    const int tid = threadIdx.x;
    const int lane = tid & 31, wid = tid >> 5;
    const int g = lane >> 2, t = lane & 3;
    const int wm = wid & 3, wn = wid >> 2;

    const float* Pbase = scores + ((size_t)bh * S + q0) * S;
    float* Sbase = soft + ((size_t)bh * S + q0) * S;
    const float* Vbase = g_V + (size_t)(b * S) * D + hd * W;

    if (tid < 128) sStats[tid] = g_stats[(size_t)bh * S + q0 + tid];
    __syncthreads();

    float acc[2][4][4] = {};

    // prefetch registers
    float4 pr[4];
    float va[4], vb[4];

    // prologue: chunk 0
#pragma unroll
    for (int p = 0; p < 4; p++) {
        int idx = tid + 256 * p;
        int row = idx >> 3;
        int c4  = (idx & 7) * 4;
        pr[p] = *reinterpret_cast<const float4*>(&Pbase[(size_t)row * S + c4]);
    }
#pragma unroll
    for (int p = 0; p < 4; p++) {
        int e    = tid + 256 * p;
        int wcol = e & 63;
        int k2   = e >> 6;
        va[p] = Vbase[(size_t)(2 * k2)     * D + wcol];
        vb[p] = Vbase[(size_t)(2 * k2 + 1) * D + wcol];
    }

    for (int k0 = 0; k0 < S; k0 += 32) {
        // store phase: exp+scale, write soft, split into smem
#pragma unroll
        for (int p = 0; p < 4; p++) {
            int idx = tid + 256 * p;
            int row = idx >> 3;
            int c4  = (idx & 7) * 4;
            float2 st = sStats[row];
            float e0 = __expf(pr[p].x - st.x) * st.y;
            float e1 = __expf(pr[p].y - st.x) * st.y;
            float e2 = __expf(pr[p].z - st.x) * st.y;
            float e3 = __expf(pr[p].w - st.x) * st.y;
            *reinterpret_cast<float4*>(&Sbase[(size_t)row * S + k0 + c4]) =
                make_float4(e0, e1, e2, e3);
            uint32_t h0, l0, h1, l1;
            splitpair(e0, e1, h0, l0);
            splitpair(e2, e3, h1, l1);
            *reinterpret_cast<uint2*>(&sPh[row][c4 >> 1]) = make_uint2(h0, h1);
            *reinterpret_cast<uint2*>(&sPl[row][c4 >> 1]) = make_uint2(l0, l1);
        }
#pragma unroll
        for (int p = 0; p < 4; p++) {
            int e    = tid + 256 * p;
            int wcol = e & 63;
            int k2   = e >> 6;
            uint32_t h, l;
            splitpair(va[p], vb[p], h, l);
            sVh[wcol][k2] = h;
            sVl[wcol][k2] = l;
        }
        __syncthreads();

        // prefetch next chunk while mma runs
        if (k0 + 32 < S) {
            const int kn = k0 + 32;
#pragma unroll
            for (int p = 0; p < 4; p++) {
                int idx = tid + 256 * p;
                int row = idx >> 3;
                int c4  = (idx & 7) * 4;
                pr[p] = *reinterpret_cast<const float4*>(&Pbase[(size_t)row * S + kn + c4]);
            }
#pragma unroll
            for (int p = 0; p < 4; p++) {
                int e    = tid + 256 * p;
                int wcol = e & 63;
                int k2   = e >> 6;
                va[p] = Vbase[(size_t)(kn + 2 * k2)     * D + wcol];
                vb[p] = Vbase[(size_t)(kn + 2 * k2 + 1) * D + wcol];
            }
        }

#pragma unroll
        for (int ka = 0; ka < 2; ka++) {
            uint32_t bh_[4][2], bl_[4][2];
#pragma unroll
            for (int na = 0; na < 4; na++) {
                int n = wn * 32 + na * 8 + g;
                bh_[na][0] = sVh[n][ka * 8 + t];
                bh_[na][1] = sVh[n][ka * 8 + t + 4];
                bl_[na][0] = sVl[n][ka * 8 + t];
                bl_[na][1] = sVl[n][ka * 8 + t + 4];
            }
#pragma unroll
            for (int ma = 0; ma < 2; ma++) {
                int r = wm * 32 + ma * 16 + g;
                int c = ka * 8 + t;
                uint32_t ah0 = sPh[r][c],     ah1 = sPh[r + 8][c];
                uint32_t ah2 = sPh[r][c + 4], ah3 = sPh[r + 8][c + 4];
                uint32_t al0 = sPl[r][c],     al1 = sPl[r + 8][c];
                uint32_t al2 = sPl[r][c + 4], al3 = sPl[r + 8][c + 4];
#pragma unroll
                for (int na = 0; na < 4; na++) {
                    float* d = acc[ma][na];
                    bmma(d[0], d[1], d[2], d[3], ah0, ah1, ah2, ah3, bh_[na][0], bh_[na][1]);
                    bmma(d[0], d[1], d[2], d[3], ah0, ah1, ah2, ah3, bl_[na][0], bl_[na][1]);
                    bmma(d[0], d[1], d[2], d[3], al0, al1, al2, al3, bh_[na][0], bh_[na][1]);
                }
            }
        }
        __syncthreads();
    }

#pragma unroll
    for (int ma = 0; ma < 2; ma++) {
#pragma unroll
        for (int na = 0; na < 4; na++) {
            int rowl = wm * 32 + ma * 16 + g;
            int coll = wn * 32 + na * 8 + 2 * t;
            float* d = acc[ma][na];
            size_t base = (size_t)(b * S + q0 + rowl) * D + hd * W + coll;
            *reinterpret_cast<float2*>(&out_h[base]) = make_float2(d[0], d[1]);
            *reinterpret_cast<float2*>(&out_h[base + (size_t)8 * D]) = make_float2(d[2], d[3]);
        }
    }
}

// ---------------------------------------------------------------------------
// Launch. d_out layout: [h | scores_soft | scores], fp32.
// ---------------------------------------------------------------------------
extern "C" void kernel_launch(void* const* d_in, const int* in_sizes, int n_in,
                              void* d_out, int out_size)
{
    using namespace cfg;
    (void)in_sizes; (void)n_in; (void)out_size;
    const float* x    = (const float*)d_in[0];
    const float* mask = (const float*)d_in[1];
    const float* wq   = (const float*)d_in[2];
    const float* bq   = (const float*)d_in[3];
    const float* wk   = (const float*)d_in[4];
    const float* bk   = (const float*)d_in[5];
    const float* wv   = (const float*)d_in[6];
    const float* bv   = (const float*)d_in[7];

    float* out   = (float*)d_out;
    float* out_h = out;
    float* out_p = out + H_ELEMS;              // scores_soft
    float* out_s = out + H_ELEMS + P_ELEMS;    // raw scores

    {
        dim3 grid(D / 128, M / 128, 3);
        qkv_gemm_kernel<<<grid, 256>>>(x, wq, bq, wk, bk, wv, bv);
    }
    {
        dim3 grid(S / 128, S / 128, B * H);
        scores_kernel<<<grid, 256>>>(mask, out_s);
    }
    {
        combine_kernel<<<ROWS / 256, 256>>>();
    }
    {
        dim3 grid(S / 128, B * H);
        pv_kernel<<<grid, 256>>>(out_s, out_p, out_h);
    }
}

// round 7
// speedup vs baseline: 2.3741x; 1.1997x over previous
#include <cuda_runtime.h>
#include <cuda_bf16.h>
#include <cstdint>

// Problem constants
namespace cfg {
constexpr int B = 2, S = 2048, D = 1024, H = 16, W = 64;
constexpr int M = B * S;                                  // 4096
constexpr int ROWS = B * H * S;                           // 65536 score rows
constexpr int KT = S / 128;                               // 16 k-tiles per row
constexpr long long H_ELEMS = (long long)B * S * D;       // 4,194,304
constexpr long long P_ELEMS = (long long)B * H * S * S;   // 134,217,728
}

// Scratch: split-bf16 operands, packed weights/V, softmax partials.
__device__ __nv_bfloat16 g_xh[cfg::M * cfg::D], g_xl[cfg::M * cfg::D];
__device__ __nv_bfloat16 g_Qh[cfg::M * cfg::D], g_Ql[cfg::M * cfg::D];
__device__ __nv_bfloat16 g_Kh[cfg::M * cfg::D], g_Kl[cfg::M * cfg::D];
__device__ __nv_bfloat16 g_Vh[cfg::M * cfg::D], g_Vl[cfg::M * cfg::D];
__device__ uint32_t g_Wph[3][(cfg::D / 2) * cfg::D];   // pair-packed weights (hi)
__device__ uint32_t g_Wpl[3][(cfg::D / 2) * cfg::D];   // (lo)
__device__ uint32_t g_Vph[(cfg::M / 2) * cfg::D];      // pair-packed V (hi)
__device__ uint32_t g_Vpl[(cfg::M / 2) * cfg::D];      // (lo)
__device__ float2 g_part[cfg::ROWS * cfg::KT];   // per (row, ktile): (max, sumexp)
__device__ float2 g_stats[cfg::ROWS];            // per row: (max, 1/sum)

// ---------------------------------------------------------------------------
// Helpers
// ---------------------------------------------------------------------------
__device__ __forceinline__ void splitone(float x, unsigned short& h, unsigned short& l)
{
    __nv_bfloat16 hb = __float2bfloat16(x);
    __nv_bfloat16 lb = __float2bfloat16(x - __bfloat162float(hb));
    h = __bfloat16_as_ushort(hb);
    l = __bfloat16_as_ushort(lb);
}

__device__ __forceinline__ void splitpair(float x0, float x1,
                                          uint32_t& hi, uint32_t& lo)
{
    unsigned short h0, l0, h1, l1;
    splitone(x0, h0, l0);
    splitone(x1, h1, l1);
    hi = ((uint32_t)h1 << 16) | h0;
    lo = ((uint32_t)l1 << 16) | l0;
}

__device__ __forceinline__ void bmma(float& d0, float& d1, float& d2, float& d3,
                                     uint32_t a0, uint32_t a1, uint32_t a2, uint32_t a3,
                                     uint32_t b0, uint32_t b1)
{
    asm volatile(
        "mma.sync.aligned.m16n8k16.row.col.f32.bf16.bf16.f32 "
        "{%0,%1,%2,%3},{%4,%5,%6,%7},{%8,%9},{%0,%1,%2,%3};\n"
        : "+f"(d0), "+f"(d1), "+f"(d2), "+f"(d3)
        : "r"(a0), "r"(a1), "r"(a2), "r"(a3), "r"(b0), "r"(b1));
}

// ---------------------------------------------------------------------------
// Prep 1: split x into hi/lo bf16 (natural layout; k-pairs contiguous).
// ---------------------------------------------------------------------------
__global__ __launch_bounds__(256) void split_x_kernel(const float* __restrict__ x)
{
    int i = blockIdx.x * 256 + threadIdx.x;      // one float4 each
    float4 v = reinterpret_cast<const float4*>(x)[i];
    ushort4 hv, lv;
    splitone(v.x, hv.x, lv.x);
    splitone(v.y, hv.y, lv.y);
    splitone(v.z, hv.z, lv.z);
    splitone(v.w, hv.w, lv.w);
    reinterpret_cast<ushort4*>(g_xh)[i] = hv;
    reinterpret_cast<ushort4*>(g_xl)[i] = lv;
}

// ---------------------------------------------------------------------------
// Prep 2: pair-pack weights along k: Wp[k2*D + n] = pack(w[2k2][n], w[2k2+1][n]).
// ---------------------------------------------------------------------------
__global__ __launch_bounds__(256) void pack_w_kernel(
    const float* __restrict__ wq, const float* __restrict__ wk,
    const float* __restrict__ wv)
{
    using namespace cfg;
    const int z = blockIdx.z;
    const float* w = (z == 0) ? wq : (z == 1) ? wk : wv;
    int idx = blockIdx.x * 256 + threadIdx.x;    // (D/2)*D = 512K
    int k2 = idx >> 10, n = idx & 1023;
    float v0 = w[(size_t)(2 * k2) * D + n];
    float v1 = w[(size_t)(2 * k2 + 1) * D + n];
    uint32_t h, l;
    splitpair(v0, v1, h, l);
    g_Wph[z][idx] = h;
    g_Wpl[z][idx] = l;
}

// ---------------------------------------------------------------------------
// Prep 3 (after qkv): pair-pack V along kpos: Vp[p*D + d] = pack(V[2p][d], V[2p+1][d]).
// ---------------------------------------------------------------------------
__global__ __launch_bounds__(256) void repack_v_kernel()
{
    using namespace cfg;
    int idx = blockIdx.x * 256 + threadIdx.x;    // M/2 * D/2 = 1M, 2 d each
    int p  = idx >> 9;
    int d2 = (idx & 511) * 2;
    uint32_t ah = *reinterpret_cast<const uint32_t*>(&g_Vh[(size_t)(2 * p) * D + d2]);
    uint32_t bh_ = *reinterpret_cast<const uint32_t*>(&g_Vh[(size_t)(2 * p + 1) * D + d2]);
    uint32_t al = *reinterpret_cast<const uint32_t*>(&g_Vl[(size_t)(2 * p) * D + d2]);
    uint32_t bl = *reinterpret_cast<const uint32_t*>(&g_Vl[(size_t)(2 * p + 1) * D + d2]);
    uint2 oh, ol;
    oh.x = __byte_perm(ah, bh_, 0x5410);
    oh.y = __byte_perm(ah, bh_, 0x7632);
    ol.x = __byte_perm(al, bl, 0x5410);
    ol.y = __byte_perm(al, bl, 0x7632);
    *reinterpret_cast<uint2*>(&g_Vph[(size_t)p * D + d2]) = oh;
    *reinterpret_cast<uint2*>(&g_Vpl[(size_t)p * D + d2]) = ol;
}

// ---------------------------------------------------------------------------
// Kernel 1: QKV projection from pre-split operands; writes split-bf16 Q/K/V.
// Tile 128x128, BK=32, reg-prefetch double buffering. 8 warps = 2(m) x 4(n).
// ---------------------------------------------------------------------------
__global__ __launch_bounds__(256) void qkv_gemm_kernel(
    const float* __restrict__ bq, const float* __restrict__ bk,
    const float* __restrict__ bv)
{
    using namespace cfg;
    const int z = blockIdx.z;
    const float* bias = (z == 0) ? bq : (z == 1) ? bk : bv;
    __nv_bfloat16* oh = (z == 0) ? g_Qh : (z == 1) ? g_Kh : g_Vh;
    __nv_bfloat16* ol = (z == 0) ? g_Ql : (z == 1) ? g_Kl : g_Vl;
    const uint32_t* wph = g_Wph[z];
    const uint32_t* wpl = g_Wpl[z];

    __shared__ __align__(16) uint32_t sAh[128][20], sAl[128][20];
    __shared__ __align__(16) uint32_t sBh[16][136], sBl[16][136];  // [k2][n]

    const int tid = threadIdx.x;
    const int lane = tid & 31, wid = tid >> 5;
    const int g = lane >> 2, t = lane & 3;
    const int wm = wid & 1, wn = wid >> 1;
    const int m0 = blockIdx.y * 128;
    const int n0 = blockIdx.x * 128;

    float acc[4][4][4] = {};
    uint4 ra[4], rb[4];

    // load chunk (k0) into registers
    auto load_regs = [&](int k0) {
#pragma unroll
        for (int p = 0; p < 4; p++) {
            int idx = tid + 256 * p;
            int rem = idx & 511;
            const __nv_bfloat16* src = (p >> 1) ? g_xl : g_xh;
            int row = rem >> 2, ch = rem & 3;
            ra[p] = *reinterpret_cast<const uint4*>(
                &src[(size_t)(m0 + row) * D + k0 + ch * 8]);
        }
#pragma unroll
        for (int p = 0; p < 4; p++) {
            int idx = tid + 256 * p;
            int rem = idx & 511;
            const uint32_t* src = (p >> 1) ? wpl : wph;
            int k2 = rem >> 5, ch = rem & 31;
            rb[p] = *reinterpret_cast<const uint4*>(
                &src[(size_t)((k0 >> 1) + k2) * D + n0 + ch * 4]);
        }
    };
    auto store_smem = [&]() {
#pragma unroll
        for (int p = 0; p < 4; p++) {
            int idx = tid + 256 * p;
            int rem = idx & 511;
            int row = rem >> 2, ch = rem & 3;
            uint32_t (*dst)[20] = (p >> 1) ? sAl : sAh;
            *reinterpret_cast<uint4*>(&dst[row][ch * 4]) = ra[p];
        }
#pragma unroll
        for (int p = 0; p < 4; p++) {
            int idx = tid + 256 * p;
            int rem = idx & 511;
            int k2 = rem >> 5, ch = rem & 31;
            uint32_t (*dst)[136] = (p >> 1) ? sBl : sBh;
            *reinterpret_cast<uint4*>(&dst[k2][ch * 4]) = rb[p];
        }
    };

    load_regs(0);
    for (int ks = 0; ks < D / 32; ks++) {
        store_smem();
        __syncthreads();
        if (ks + 1 < D / 32) load_regs((ks + 1) * 32);

#pragma unroll
        for (int ka = 0; ka < 2; ka++) {
            uint32_t bh[4][2], bl[4][2];
#pragma unroll
            for (int na = 0; na < 4; na++) {
                int n = wn * 32 + na * 8 + g;
                bh[na][0] = sBh[ka * 8 + t][n];
                bh[na][1] = sBh[ka * 8 + t + 4][n];
                bl[na][0] = sBl[ka * 8 + t][n];
                bl[na][1] = sBl[ka * 8 + t + 4][n];
            }
#pragma unroll
            for (int ma = 0; ma < 4; ma++) {
                int r = wm * 64 + ma * 16 + g;
                int c = ka * 8 + t;
                uint32_t ah0 = sAh[r][c],     ah1 = sAh[r + 8][c];
                uint32_t ah2 = sAh[r][c + 4], ah3 = sAh[r + 8][c + 4];
                uint32_t al0 = sAl[r][c],     al1 = sAl[r + 8][c];
                uint32_t al2 = sAl[r][c + 4], al3 = sAl[r + 8][c + 4];
#pragma unroll
                for (int na = 0; na < 4; na++) {
                    float* d = acc[ma][na];
                    bmma(d[0], d[1], d[2], d[3], ah0, ah1, ah2, ah3, bh[na][0], bh[na][1]);
                    bmma(d[0], d[1], d[2], d[3], ah0, ah1, ah2, ah3, bl[na][0], bl[na][1]);
                    bmma(d[0], d[1], d[2], d[3], al0, al1, al2, al3, bh[na][0], bh[na][1]);
                }
            }
        }
        __syncthreads();
    }

    // Epilogue: add bias, write split-bf16.
#pragma unroll
    for (int ma = 0; ma < 4; ma++) {
#pragma unroll
        for (int na = 0; na < 4; na++) {
            int row = m0 + wm * 64 + ma * 16 + g;
            int col = n0 + wn * 32 + na * 8 + 2 * t;
            float b0 = bias[col], b1 = bias[col + 1];
            float* d = acc[ma][na];
            float v0 = d[0] + b0, v1 = d[1] + b1;
            float v2 = d[2] + b0, v3 = d[3] + b1;
            ushort2 hv, lv;
            splitone(v0, hv.x, lv.x);
            splitone(v1, hv.y, lv.y);
            *reinterpret_cast<ushort2*>(&oh[(size_t)row * D + col]) = hv;
            *reinterpret_cast<ushort2*>(&ol[(size_t)row * D + col]) = lv;
            splitone(v2, hv.x, lv.x);
            splitone(v3, hv.y, lv.y);
            *reinterpret_cast<ushort2*>(&oh[(size_t)(row + 8) * D + col]) = hv;
            *reinterpret_cast<ushort2*>(&ol[(size_t)(row + 8) * D + col]) = lv;
        }
    }
}

// ---------------------------------------------------------------------------
// Kernel 2: scores = Q Kt / 8 - 10000*(1-mask) + per-(row,128-tile) partials.
// Pre-split bf16 operands; 2 chunks of 32 w with reg-prefetch.
// ---------------------------------------------------------------------------
__global__ __launch_bounds__(256) void scores_kernel(
    const float* __restrict__ mask, float* __restrict__ out_s)
{
    using namespace cfg;
    const int bh = blockIdx.z;
    const int b  = bh >> 4, hd = bh & 15;
    const int q0 = blockIdx.y * 128;
    const int k0 = blockIdx.x * 128;

    __shared__ __align__(16) uint32_t sQh[128][20], sQl[128][20];
    __shared__ __align__(16) uint32_t sKh[128][20], sKl[128][20];
    __shared__ float redM[128][4];
    __shared__ float redS[128][4];

    const int tid = threadIdx.x;
    const int lane = tid & 31, wid = tid >> 5;
    const int g = lane >> 2, t = lane & 3;
    const int wm = wid & 1, wn = wid >> 1;

    const __nv_bfloat16* gsrc[4] = {
        g_Qh + (size_t)(b * S + q0) * D + hd * W,
        g_Ql + (size_t)(b * S + q0) * D + hd * W,
        g_Kh + (size_t)(b * S + k0) * D + hd * W,
        g_Kl + (size_t)(b * S + k0) * D + hd * W };

    float acc[4][4][4] = {};
    uint4 st[8];

    auto load_regs = [&](int w0) {
#pragma unroll
        for (int p = 0; p < 8; p++) {
            int idx = tid + 256 * p;
            int rem = idx & 511;
            int row = rem >> 2, ch = rem & 3;
            st[p] = *reinterpret_cast<const uint4*>(
                &gsrc[p >> 1][(size_t)row * D + w0 + ch * 8]);
        }
    };
    auto store_smem = [&]() {
#pragma unroll
        for (int p = 0; p < 8; p++) {
            int idx = tid + 256 * p;
            int rem = idx & 511;
            int row = rem >> 2, ch = rem & 3;
            uint32_t (*dst)[20] = (p >> 1 == 0) ? sQh : (p >> 1 == 1) ? sQl
                                 : (p >> 1 == 2) ? sKh : sKl;
            *reinterpret_cast<uint4*>(&dst[row][ch * 4]) = st[p];
        }
    };
    auto mma_chunk = [&]() {
#pragma unroll
        for (int ka = 0; ka < 2; ka++) {
            uint32_t bh_[4][2], bl_[4][2];
#pragma unroll
            for (int na = 0; na < 4; na++) {
                int n = wn * 32 + na * 8 + g;
                bh_[na][0] = sKh[n][ka * 8 + t];
                bh_[na][1] = sKh[n][ka * 8 + t + 4];
                bl_[na][0] = sKl[n][ka * 8 + t];
                bl_[na][1] = sKl[n][ka * 8 + t + 4];
            }
#pragma unroll
            for (int ma = 0; ma < 4; ma++) {
                int r = wm * 64 + ma * 16 + g;
                int c = ka * 8 + t;
                uint32_t ah0 = sQh[r][c],     ah1 = sQh[r + 8][c];
                uint32_t ah2 = sQh[r][c + 4], ah3 = sQh[r + 8][c + 4];
                uint32_t al0 = sQl[r][c],     al1 = sQl[r + 8][c];
                uint32_t al2 = sQl[r][c + 4], al3 = sQl[r + 8][c + 4];
#pragma unroll
                for (int na = 0; na < 4; na++) {
                    float* d = acc[ma][na];
                    bmma(d[0], d[1], d[2], d[3], ah0, ah1, ah2, ah3, bh_[na][0], bh_[na][1]);
                    bmma(d[0], d[1], d[2], d[3], ah0, ah1, ah2, ah3, bl_[na][0], bl_[na][1]);
                    bmma(d[0], d[1], d[2], d[3], al0, al1, al2, al3, bh_[na][0], bh_[na][1]);
                }
            }
        }
    };

    load_regs(0);
    store_smem();
    __syncthreads();
    load_regs(32);          // prefetch chunk 1 (overlaps chunk-0 MMAs)
    mma_chunk();
    __syncthreads();
    store_smem();
    __syncthreads();
    mma_chunk();

    // Scale + mask, store scores, softmax partials.
    const float scale = 0.125f;
    float* dst = out_s + ((size_t)bh * S + q0) * S + k0;
    float rmax[4][2];
#pragma unroll
    for (int ma = 0; ma < 4; ma++) { rmax[ma][0] = -1e30f; rmax[ma][1] = -1e30f; }

#pragma unroll
    for (int ma = 0; ma < 4; ma++) {
#pragma unroll
        for (int na = 0; na < 4; na++) {
            int rowl = wm * 64 + ma * 16 + g;
            int coll = wn * 32 + na * 8 + 2 * t;
            float m0v = mask[b * S + k0 + coll];
            float m1v = mask[b * S + k0 + coll + 1];
            float a0 = -10000.0f * (1.0f - m0v);
            float a1 = -10000.0f * (1.0f - m1v);
            float* d = acc[ma][na];
            float v0 = d[0] * scale + a0, v1 = d[1] * scale + a1;
            float v2 = d[2] * scale + a0, v3 = d[3] * scale + a1;
            d[0] = v0; d[1] = v1; d[2] = v2; d[3] = v3;
            *reinterpret_cast<float2*>(&dst[(size_t)rowl * S + coll]) = make_float2(v0, v1);
            *reinterpret_cast<float2*>(&dst[(size_t)(rowl + 8) * S + coll]) = make_float2(v2, v3);
            rmax[ma][0] = fmaxf(rmax[ma][0], fmaxf(v0, v1));
            rmax[ma][1] = fmaxf(rmax[ma][1], fmaxf(v2, v3));
        }
    }
#pragma unroll
    for (int ma = 0; ma < 4; ma++)
#pragma unroll
        for (int hf = 0; hf < 2; hf++) {
            float m = rmax[ma][hf];
            m = fmaxf(m, __shfl_xor_sync(0xffffffffu, m, 1));
            m = fmaxf(m, __shfl_xor_sync(0xffffffffu, m, 2));
            rmax[ma][hf] = m;
        }
    if (t == 0) {
#pragma unroll
        for (int ma = 0; ma < 4; ma++)
#pragma unroll
            for (int hf = 0; hf < 2; hf++)
                redM[wm * 64 + ma * 16 + g + hf * 8][wn] = rmax[ma][hf];
    }
    __syncthreads();

    float se[4][2];
#pragma unroll
    for (int ma = 0; ma < 4; ma++)
#pragma unroll
        for (int hf = 0; hf < 2; hf++) {
            int row = wm * 64 + ma * 16 + g + hf * 8;
            float m = fmaxf(fmaxf(redM[row][0], redM[row][1]),
                            fmaxf(redM[row][2], redM[row][3]));
            rmax[ma][hf] = m;
            se[ma][hf] = 0.0f;
        }
#pragma unroll
    for (int ma = 0; ma < 4; ma++)
#pragma unroll
        for (int na = 0; na < 4; na++) {
            float* d = acc[ma][na];
            se[ma][0] += __expf(d[0] - rmax[ma][0]) + __expf(d[1] - rmax[ma][0]);
            se[ma][1] += __expf(d[2] - rmax[ma][1]) + __expf(d[3] - rmax[ma][1]);
        }
#pragma unroll
    for (int ma = 0; ma < 4; ma++)
#pragma unroll
        for (int hf = 0; hf < 2; hf++) {
            float s = se[ma][hf];
            s += __shfl_xor_sync(0xffffffffu, s, 1);
            s += __shfl_xor_sync(0xffffffffu, s, 2);
            se[ma][hf] = s;
        }
    if (t == 0) {
#pragma unroll
        for (int ma = 0; ma < 4; ma++)
#pragma unroll
            for (int hf = 0; hf < 2; hf++)
                redS[wm * 64 + ma * 16 + g + hf * 8][wn] = se[ma][hf];
    }
    __syncthreads();

    if (tid < 128) {
        int row = tid;
        float m = fmaxf(fmaxf(redM[row][0], redM[row][1]),
                        fmaxf(redM[row][2], redM[row][3]));
        float s = redS[row][0] + redS[row][1] + redS[row][2] + redS[row][3];
        g_part[((size_t)bh * S + q0 + row) * KT + blockIdx.x] = make_float2(m, s);
    }
}

// ---------------------------------------------------------------------------
// Kernel 3: combine per-row tile partials -> (max, 1/sum)
// ---------------------------------------------------------------------------
__global__ __launch_bounds__(256) void combine_kernel()
{
    using namespace cfg;
    int row = blockIdx.x * 256 + threadIdx.x;
    const float2* p = &g_part[(size_t)row * KT];
    float m = -1e30f;
#pragma unroll
    for (int i = 0; i < KT; i++) m = fmaxf(m, p[i].x);
    float s = 0.0f;
#pragma unroll
    for (int i = 0; i < KT; i++) s += p[i].y * __expf(p[i].x - m);
    g_stats[row] = make_float2(m, 1.0f / s);
}

// ---------------------------------------------------------------------------
// Kernel 4: fused softmax-apply + P@V. Reads raw scores + packed V,
// writes soft + h. Tile 128(q) x 64(w), BK=32, reg-prefetch.
// ---------------------------------------------------------------------------
__global__ __launch_bounds__(256, 2) void pv_kernel(
    const float* __restrict__ scores, float* __restrict__ soft,
    float* __restrict__ out_h)
{
    using namespace cfg;
    const int bh = blockIdx.y;
    const int b  = bh >> 4, hd = bh & 15;
    const int q0 = blockIdx.x * 128;

    __shared__ __align__(16) uint32_t sPh[128][20], sPl[128][20];
    __shared__ __align__(16) uint32_t sVh[16][72],  sVl[16][72];   // [k2][w]
    __shared__ float2 sStats[128];

    const int tid = threadIdx.x;
    const int lane = tid & 31, wid = tid >> 5;
    const int g = lane >> 2, t = lane & 3;
    const int wm = wid & 3, wn = wid >> 2;

    const float* Pbase = scores + ((size_t)bh * S + q0) * S;
    float* Sbase = soft + ((size_t)bh * S + q0) * S;
    const size_t vpair0 = (size_t)(b * S) / 2;

    if (tid < 128) sStats[tid] = g_stats[(size_t)bh * S + q0 + tid];
    __syncthreads();

    float acc[2][4][4] = {};
    float4 pr[4];
    uint4 rv[2];

    auto load_v = [&](int k0) {
#pragma unroll
        for (int p = 0; p < 2; p++) {
            int idx = tid & 255;
            int k2 = idx >> 4, ch = idx & 15;
            const uint32_t* src = p ? g_Vpl : g_Vph;
            rv[p] = *reinterpret_cast<const uint4*>(
                &src[(vpair0 + (k0 >> 1) + k2) * D + hd * W + ch * 4]);
        }
    };
    auto load_p = [&](int k0) {
#pragma unroll
        for (int p = 0; p < 4; p++) {
            int idx = tid + 256 * p;
            int row = idx >> 3;
            int c4  = (idx & 7) * 4;
            pr[p] = *reinterpret_cast<const float4*>(&Pbase[(size_t)row * S + k0 + c4]);
        }
    };

    load_p(0);
    load_v(0);

    for (int k0 = 0; k0 < S; k0 += 32) {
        // exp + write soft + split into smem
#pragma unroll
        for (int p = 0; p < 4; p++) {
            int idx = tid + 256 * p;
            int row = idx >> 3;
            int c4  = (idx & 7) * 4;
            float2 stt = sStats[row];
            float e0 = __expf(pr[p].x - stt.x) * stt.y;
            float e1 = __expf(pr[p].y - stt.x) * stt.y;
            float e2 = __expf(pr[p].z - stt.x) * stt.y;
            float e3 = __expf(pr[p].w - stt.x) * stt.y;
            *reinterpret_cast<float4*>(&Sbase[(size_t)row * S + k0 + c4]) =
                make_float4(e0, e1, e2, e3);
            uint32_t h0, l0, h1, l1;
            splitpair(e0, e1, h0, l0);
            splitpair(e2, e3, h1, l1);
            *reinterpret_cast<uint2*>(&sPh[row][c4 >> 1]) = make_uint2(h0, h1);
            *reinterpret_cast<uint2*>(&sPl[row][c4 >> 1]) = make_uint2(l0, l1);
        }
        {
            int idx = tid & 255;
            int k2 = idx >> 4, ch = idx & 15;
            *reinterpret_cast<uint4*>(&sVh[k2][ch * 4]) = rv[0];
            *reinterpret_cast<uint4*>(&sVl[k2][ch * 4]) = rv[1];
        }
        __syncthreads();

        if (k0 + 32 < S) {
            load_p(k0 + 32);
            load_v(k0 + 32);
        }

#pragma unroll
        for (int ka = 0; ka < 2; ka++) {
            uint32_t bh_[4][2], bl_[4][2];
#pragma unroll
            for (int na = 0; na < 4; na++) {
                int n = wn * 32 + na * 8 + g;
                bh_[na][0] = sVh[ka * 8 + t][n];
                bh_[na][1] = sVh[ka * 8 + t + 4][n];
                bl_[na][0] = sVl[ka * 8 + t][n];
                bl_[na][1] = sVl[ka * 8 + t + 4][n];
            }
#pragma unroll
            for (int ma = 0; ma < 2; ma++) {
                int r = wm * 32 + ma * 16 + g;
                int c = ka * 8 + t;
                uint32_t ah0 = sPh[r][c],     ah1 = sPh[r + 8][c];
                uint32_t ah2 = sPh[r][c + 4], ah3 = sPh[r + 8][c + 4];
                uint32_t al0 = sPl[r][c],     al1 = sPl[r + 8][c];
                uint32_t al2 = sPl[r][c + 4], al3 = sPl[r + 8][c + 4];
#pragma unroll
                for (int na = 0; na < 4; na++) {
                    float* d = acc[ma][na];
                    bmma(d[0], d[1], d[2], d[3], ah0, ah1, ah2, ah3, bh_[na][0], bh_[na][1]);
                    bmma(d[0], d[1], d[2], d[3], ah0, ah1, ah2, ah3, bl_[na][0], bl_[na][1]);
                    bmma(d[0], d[1], d[2], d[3], al0, al1, al2, al3, bh_[na][0], bh_[na][1]);
                }
            }
        }
        __syncthreads();
    }

#pragma unroll
    for (int ma = 0; ma < 2; ma++) {
#pragma unroll
        for (int na = 0; na < 4; na++) {
            int rowl = wm * 32 + ma * 16 + g;
            int coll = wn * 32 + na * 8 + 2 * t;
            float* d = acc[ma][na];
            size_t base = (size_t)(b * S + q0 + rowl) * D + hd * W + coll;
            *reinterpret_cast<float2*>(&out_h[base]) = make_float2(d[0], d[1]);
            *reinterpret_cast<float2*>(&out_h[base + (size_t)8 * D]) = make_float2(d[2], d[3]);
        }
    }
}

// ---------------------------------------------------------------------------
// Launch. d_out layout: [h | scores_soft | scores], fp32.
// ---------------------------------------------------------------------------
extern "C" void kernel_launch(void* const* d_in, const int* in_sizes, int n_in,
                              void* d_out, int out_size)
{
    using namespace cfg;
    (void)in_sizes; (void)n_in; (void)out_size;
    const float* x    = (const float*)d_in[0];
    const float* mask = (const float*)d_in[1];
    const float* wq   = (const float*)d_in[2];
    const float* bq   = (const float*)d_in[3];
    const float* wk   = (const float*)d_in[4];
    const float* bk   = (const float*)d_in[5];
    const float* wv   = (const float*)d_in[6];
    const float* bv   = (const float*)d_in[7];

    float* out   = (float*)d_out;
    float* out_h = out;
    float* out_p = out + H_ELEMS;              // scores_soft
    float* out_s = out + H_ELEMS + P_ELEMS;    // raw scores

    split_x_kernel<<<M * D / 4 / 256, 256>>>(x);
    {
        dim3 grid((D / 2) * D / 256, 1, 3);
        pack_w_kernel<<<grid, 256>>>(wq, wk, wv);
    }
    {
        dim3 grid(D / 128, M / 128, 3);
        qkv_gemm_kernel<<<grid, 256>>>(bq, bk, bv);
    }
    repack_v_kernel<<<(M / 2) * (D / 2) / 256, 256>>>();
    {
        dim3 grid(S / 128, S / 128, B * H);
        scores_kernel<<<grid, 256>>>(mask, out_s);
    }
    combine_kernel<<<ROWS / 256, 256>>>();
    {
        dim3 grid(S / 128, B * H);
        pv_kernel<<<grid, 256>>>(out_s, out_p, out_h);
    }
}

// round 9
// speedup vs baseline: 2.4600x; 1.0362x over previous
#include <cuda_runtime.h>
#include <cuda_bf16.h>
#include <cstdint>

// Problem constants
namespace cfg {
constexpr int B = 2, S = 2048, D = 1024, H = 16, W = 64;
constexpr int M = B * S;                                  // 4096
constexpr int ROWS = B * H * S;                           // 65536 score rows
constexpr int KT = S / 128;                               // 16 k-tiles per row
constexpr long long H_ELEMS = (long long)B * S * D;       // 4,194,304
constexpr long long P_ELEMS = (long long)B * H * S * S;   // 134,217,728
}

// Scratch: split-bf16 operands, packed weights/V, softmax partials.
__device__ __nv_bfloat16 g_xh[cfg::M * cfg::D], g_xl[cfg::M * cfg::D];
__device__ __nv_bfloat16 g_Qh[cfg::M * cfg::D], g_Ql[cfg::M * cfg::D];
__device__ __nv_bfloat16 g_Kh[cfg::M * cfg::D], g_Kl[cfg::M * cfg::D];
__device__ __nv_bfloat16 g_Vh[cfg::M * cfg::D], g_Vl[cfg::M * cfg::D];
__device__ uint32_t g_Wph[3][(cfg::D / 2) * cfg::D];   // pair-packed weights (hi)
__device__ uint32_t g_Wpl[3][(cfg::D / 2) * cfg::D];   // (lo)
__device__ uint32_t g_Vph[(cfg::M / 2) * cfg::D];      // pair-packed V (hi)
__device__ uint32_t g_Vpl[(cfg::M / 2) * cfg::D];      // (lo)
__device__ float g_part[cfg::ROWS * cfg::KT];    // per (row, ktile): sumexp
__device__ float g_stats[cfg::ROWS];             // per row: 1/sum

// ---------------------------------------------------------------------------
// Helpers
// ---------------------------------------------------------------------------
__device__ __forceinline__ void splitone(float x, unsigned short& h, unsigned short& l)
{
    __nv_bfloat16 hb = __float2bfloat16(x);
    __nv_bfloat16 lb = __float2bfloat16(x - __bfloat162float(hb));
    h = __bfloat16_as_ushort(hb);
    l = __bfloat16_as_ushort(lb);
}

__device__ __forceinline__ void splitpair(float x0, float x1,
                                          uint32_t& hi, uint32_t& lo)
{
    unsigned short h0, l0, h1, l1;
    splitone(x0, h0, l0);
    splitone(x1, h1, l1);
    hi = ((uint32_t)h1 << 16) | h0;
    lo = ((uint32_t)l1 << 16) | l0;
}

__device__ __forceinline__ void bmma(float& d0, float& d1, float& d2, float& d3,
                                     uint32_t a0, uint32_t a1, uint32_t a2, uint32_t a3,
                                     uint32_t b0, uint32_t b1)
{
    asm volatile(
        "mma.sync.aligned.m16n8k16.row.col.f32.bf16.bf16.f32 "
        "{%0,%1,%2,%3},{%4,%5,%6,%7},{%8,%9},{%0,%1,%2,%3};\n"
        : "+f"(d0), "+f"(d1), "+f"(d2), "+f"(d3)
        : "r"(a0), "r"(a1), "r"(a2), "r"(a3), "r"(b0), "r"(b1));
}

// ---------------------------------------------------------------------------
// Prep 1: split x into hi/lo bf16.
// ---------------------------------------------------------------------------
__global__ __launch_bounds__(256) void split_x_kernel(const float* __restrict__ x)
{
    int i = blockIdx.x * 256 + threadIdx.x;
    float4 v = reinterpret_cast<const float4*>(x)[i];
    ushort4 hv, lv;
    splitone(v.x, hv.x, lv.x);
    splitone(v.y, hv.y, lv.y);
    splitone(v.z, hv.z, lv.z);
    splitone(v.w, hv.w, lv.w);
    reinterpret_cast<ushort4*>(g_xh)[i] = hv;
    reinterpret_cast<ushort4*>(g_xl)[i] = lv;
}

// ---------------------------------------------------------------------------
// Prep 2: pair-pack weights along k.
// ---------------------------------------------------------------------------
__global__ __launch_bounds__(256) void pack_w_kernel(
    const float* __restrict__ wq, const float* __restrict__ wk,
    const float* __restrict__ wv)
{
    using namespace cfg;
    const int z = blockIdx.z;
    const float* w = (z == 0) ? wq : (z == 1) ? wk : wv;
    int idx = blockIdx.x * 256 + threadIdx.x;
    int k2 = idx >> 10, n = idx & 1023;
    float v0 = w[(size_t)(2 * k2) * D + n];
    float v1 = w[(size_t)(2 * k2 + 1) * D + n];
    uint32_t h, l;
    splitpair(v0, v1, h, l);
    g_Wph[z][idx] = h;
    g_Wpl[z][idx] = l;
}

// ---------------------------------------------------------------------------
// Prep 3 (after qkv): pair-pack V (hi+lo) along kpos.
// ---------------------------------------------------------------------------
__global__ __launch_bounds__(256) void repack_v_kernel()
{
    using namespace cfg;
    int idx = blockIdx.x * 256 + threadIdx.x;    // M/2 * D/2, 2 d each
    int p  = idx >> 9;
    int d2 = (idx & 511) * 2;
    uint32_t ah = *reinterpret_cast<const uint32_t*>(&g_Vh[(size_t)(2 * p) * D + d2]);
    uint32_t bh_ = *reinterpret_cast<const uint32_t*>(&g_Vh[(size_t)(2 * p + 1) * D + d2]);
    uint32_t al = *reinterpret_cast<const uint32_t*>(&g_Vl[(size_t)(2 * p) * D + d2]);
    uint32_t bl = *reinterpret_cast<const uint32_t*>(&g_Vl[(size_t)(2 * p + 1) * D + d2]);
    uint2 oh, ol;
    oh.x = __byte_perm(ah, bh_, 0x5410);
    oh.y = __byte_perm(ah, bh_, 0x7632);
    ol.x = __byte_perm(al, bl, 0x5410);
    ol.y = __byte_perm(al, bl, 0x7632);
    *reinterpret_cast<uint2*>(&g_Vph[(size_t)p * D + d2]) = oh;
    *reinterpret_cast<uint2*>(&g_Vpl[(size_t)p * D + d2]) = ol;
}

// ---------------------------------------------------------------------------
// Kernel 1: QKV projection (split-bf16 3-term); writes split-bf16 Q/K/V.
// ---------------------------------------------------------------------------
__global__ __launch_bounds__(256) void qkv_gemm_kernel(
    const float* __restrict__ bq, const float* __restrict__ bk,
    const float* __restrict__ bv)
{
    using namespace cfg;
    const int z = blockIdx.z;
    const float* bias = (z == 0) ? bq : (z == 1) ? bk : bv;
    __nv_bfloat16* oh = (z == 0) ? g_Qh : (z == 1) ? g_Kh : g_Vh;
    __nv_bfloat16* ol = (z == 0) ? g_Ql : (z == 1) ? g_Kl : g_Vl;
    const uint32_t* wph = g_Wph[z];
    const uint32_t* wpl = g_Wpl[z];

    __shared__ __align__(16) uint32_t sAh[128][20], sAl[128][20];
    __shared__ __align__(16) uint32_t sBh[16][136], sBl[16][136];

    const int tid = threadIdx.x;
    const int lane = tid & 31, wid = tid >> 5;
    const int g = lane >> 2, t = lane & 3;
    const int wm = wid & 1, wn = wid >> 1;
    const int m0 = blockIdx.y * 128;
    const int n0 = blockIdx.x * 128;

    float acc[4][4][4] = {};
    uint4 ra[4], rb[4];

    auto load_regs = [&](int k0) {
#pragma unroll
        for (int p = 0; p < 4; p++) {
            int idx = tid + 256 * p;
            int rem = idx & 511;
            const __nv_bfloat16* src = (p >> 1) ? g_xl : g_xh;
            int row = rem >> 2, ch = rem & 3;
            ra[p] = *reinterpret_cast<const uint4*>(
                &src[(size_t)(m0 + row) * D + k0 + ch * 8]);
        }
#pragma unroll
        for (int p = 0; p < 4; p++) {
            int idx = tid + 256 * p;
            int rem = idx & 511;
            const uint32_t* src = (p >> 1) ? wpl : wph;
            int k2 = rem >> 5, ch = rem & 31;
            rb[p] = *reinterpret_cast<const uint4*>(
                &src[(size_t)((k0 >> 1) + k2) * D + n0 + ch * 4]);
        }
    };
    auto store_smem = [&]() {
#pragma unroll
        for (int p = 0; p < 4; p++) {
            int idx = tid + 256 * p;
            int rem = idx & 511;
            int row = rem >> 2, ch = rem & 3;
            uint32_t (*dst)[20] = (p >> 1) ? sAl : sAh;
            *reinterpret_cast<uint4*>(&dst[row][ch * 4]) = ra[p];
        }
#pragma unroll
        for (int p = 0; p < 4; p++) {
            int idx = tid + 256 * p;
            int rem = idx & 511;
            int k2 = rem >> 5, ch = rem & 31;
            uint32_t (*dst)[136] = (p >> 1) ? sBl : sBh;
            *reinterpret_cast<uint4*>(&dst[k2][ch * 4]) = rb[p];
        }
    };

    load_regs(0);
    for (int ks = 0; ks < D / 32; ks++) {
        store_smem();
        __syncthreads();
        if (ks + 1 < D / 32) load_regs((ks + 1) * 32);

#pragma unroll
        for (int ka = 0; ka < 2; ka++) {
            uint32_t bh[4][2], bl[4][2];
#pragma unroll
            for (int na = 0; na < 4; na++) {
                int n = wn * 32 + na * 8 + g;
                bh[na][0] = sBh[ka * 8 + t][n];
                bh[na][1] = sBh[ka * 8 + t + 4][n];
                bl[na][0] = sBl[ka * 8 + t][n];
                bl[na][1] = sBl[ka * 8 + t + 4][n];
            }
#pragma unroll
            for (int ma = 0; ma < 4; ma++) {
                int r = wm * 64 + ma * 16 + g;
                int c = ka * 8 + t;
                uint32_t ah0 = sAh[r][c],     ah1 = sAh[r + 8][c];
                uint32_t ah2 = sAh[r][c + 4], ah3 = sAh[r + 8][c + 4];
                uint32_t al0 = sAl[r][c],     al1 = sAl[r + 8][c];
                uint32_t al2 = sAl[r][c + 4], al3 = sAl[r + 8][c + 4];
#pragma unroll
                for (int na = 0; na < 4; na++) {
                    float* d = acc[ma][na];
                    bmma(d[0], d[1], d[2], d[3], ah0, ah1, ah2, ah3, bh[na][0], bh[na][1]);
                    bmma(d[0], d[1], d[2], d[3], ah0, ah1, ah2, ah3, bl[na][0], bl[na][1]);
                    bmma(d[0], d[1], d[2], d[3], al0, al1, al2, al3, bh[na][0], bh[na][1]);
                }
            }
        }
        __syncthreads();
    }

#pragma unroll
    for (int ma = 0; ma < 4; ma++) {
#pragma unroll
        for (int na = 0; na < 4; na++) {
            int row = m0 + wm * 64 + ma * 16 + g;
            int col = n0 + wn * 32 + na * 8 + 2 * t;
            float b0 = bias[col], b1 = bias[col + 1];
            float* d = acc[ma][na];
            float v0 = d[0] + b0, v1 = d[1] + b1;
            float v2 = d[2] + b0, v3 = d[3] + b1;
            ushort2 hv, lv;
            splitone(v0, hv.x, lv.x);
            splitone(v1, hv.y, lv.y);
            *reinterpret_cast<ushort2*>(&oh[(size_t)row * D + col]) = hv;
            *reinterpret_cast<ushort2*>(&ol[(size_t)row * D + col]) = lv;
            splitone(v2, hv.x, lv.x);
            splitone(v3, hv.y, lv.y);
            *reinterpret_cast<ushort2*>(&oh[(size_t)(row + 8) * D + col]) = hv;
            *reinterpret_cast<ushort2*>(&ol[(size_t)(row + 8) * D + col]) = lv;
        }
    }
}

// ---------------------------------------------------------------------------
// Kernel 2: scores = Q Kt / 8 - 10000*(1-mask); per-(row,128-tile) sumexp
// partials (no max: exp(v) directly, masked entries underflow to 0).
// ---------------------------------------------------------------------------
__global__ __launch_bounds__(256) void scores_kernel(
    const float* __restrict__ mask, float* __restrict__ out_s)
{
    using namespace cfg;
    const int bh = blockIdx.z;
    const int b  = bh >> 4, hd = bh & 15;
    const int q0 = blockIdx.y * 128;
    const int k0 = blockIdx.x * 128;

    __shared__ __align__(16) uint32_t sQh[128][20], sQl[128][20];
    __shared__ __align__(16) uint32_t sKh[128][20], sKl[128][20];
    __shared__ float redS[128][4];

    const int tid = threadIdx.x;
    const int lane = tid & 31, wid = tid >> 5;
    const int g = lane >> 2, t = lane & 3;
    const int wm = wid & 1, wn = wid >> 1;

    const __nv_bfloat16* gsrc[4] = {
        g_Qh + (size_t)(b * S + q0) * D + hd * W,
        g_Ql + (size_t)(b * S + q0) * D + hd * W,
        g_Kh + (size_t)(b * S + k0) * D + hd * W,
        g_Kl + (size_t)(b * S + k0) * D + hd * W };

    float acc[4][4][4] = {};
    uint4 st[8];

    auto load_regs = [&](int w0) {
#pragma unroll
        for (int p = 0; p < 8; p++) {
            int idx = tid + 256 * p;
            int rem = idx & 511;
            int row = rem >> 2, ch = rem & 3;
            st[p] = *reinterpret_cast<const uint4*>(
                &gsrc[p >> 1][(size_t)row * D + w0 + ch * 8]);
        }
    };
    auto store_smem = [&]() {
#pragma unroll
        for (int p = 0; p < 8; p++) {
            int idx = tid + 256 * p;
            int rem = idx & 511;
            int row = rem >> 2, ch = rem & 3;
            uint32_t (*dst)[20] = (p >> 1 == 0) ? sQh : (p >> 1 == 1) ? sQl
                                 : (p >> 1 == 2) ? sKh : sKl;
            *reinterpret_cast<uint4*>(&dst[row][ch * 4]) = st[p];
        }
    };
    auto mma_chunk = [&]() {
#pragma unroll
        for (int ka = 0; ka < 2; ka++) {
            uint32_t bh_[4][2], bl_[4][2];
#pragma unroll
            for (int na = 0; na < 4; na++) {
                int n = wn * 32 + na * 8 + g;
                bh_[na][0] = sKh[n][ka * 8 + t];
                bh_[na][1] = sKh[n][ka * 8 + t + 4];
                bl_[na][0] = sKl[n][ka * 8 + t];
                bl_[na][1] = sKl[n][ka * 8 + t + 4];
            }
#pragma unroll
            for (int ma = 0; ma < 4; ma++) {
                int r = wm * 64 + ma * 16 + g;
                int c = ka * 8 + t;
                uint32_t ah0 = sQh[r][c],     ah1 = sQh[r + 8][c];
                uint32_t ah2 = sQh[r][c + 4], ah3 = sQh[r + 8][c + 4];
                uint32_t al0 = sQl[r][c],     al1 = sQl[r + 8][c];
                uint32_t al2 = sQl[r][c + 4], al3 = sQl[r + 8][c + 4];
#pragma unroll
                for (int na = 0; na < 4; na++) {
                    float* d = acc[ma][na];
                    bmma(d[0], d[1], d[2], d[3], ah0, ah1, ah2, ah3, bh_[na][0], bh_[na][1]);
                    bmma(d[0], d[1], d[2], d[3], ah0, ah1, ah2, ah3, bl_[na][0], bl_[na][1]);
                    bmma(d[0], d[1], d[2], d[3], al0, al1, al2, al3, bh_[na][0], bh_[na][1]);
                }
            }
        }
    };

    load_regs(0);
    store_smem();
    __syncthreads();
    load_regs(32);
    mma_chunk();
    __syncthreads();
    store_smem();
    __syncthreads();
    mma_chunk();

    // Scale + mask, store scores, accumulate sumexp partials (no max).
    const float scale = 0.125f;
    float* dst = out_s + ((size_t)bh * S + q0) * S + k0;
    float se[4][2] = {};

#pragma unroll
    for (int ma = 0; ma < 4; ma++) {
#pragma unroll
        for (int na = 0; na < 4; na++) {
            int rowl = wm * 64 + ma * 16 + g;
            int coll = wn * 32 + na * 8 + 2 * t;
            float m0v = mask[b * S + k0 + coll];
            float m1v = mask[b * S + k0 + coll + 1];
            float a0 = -10000.0f * (1.0f - m0v);
            float a1 = -10000.0f * (1.0f - m1v);
            float* d = acc[ma][na];
            float v0 = d[0] * scale + a0, v1 = d[1] * scale + a1;
            float v2 = d[2] * scale + a0, v3 = d[3] * scale + a1;
            *reinterpret_cast<float2*>(&dst[(size_t)rowl * S + coll]) = make_float2(v0, v1);
            *reinterpret_cast<float2*>(&dst[(size_t)(rowl + 8) * S + coll]) = make_float2(v2, v3);
            se[ma][0] += __expf(v0) + __expf(v1);
            se[ma][1] += __expf(v2) + __expf(v3);
        }
    }
#pragma unroll
    for (int ma = 0; ma < 4; ma++)
#pragma unroll
        for (int hf = 0; hf < 2; hf++) {
            float s = se[ma][hf];
            s += __shfl_xor_sync(0xffffffffu, s, 1);
            s += __shfl_xor_sync(0xffffffffu, s, 2);
            se[ma][hf] = s;
        }
    if (t == 0) {
#pragma unroll
        for (int ma = 0; ma < 4; ma++)
#pragma unroll
            for (int hf = 0; hf < 2; hf++)
                redS[wm * 64 + ma * 16 + g + hf * 8][wn] = se[ma][hf];
    }
    __syncthreads();

    if (tid < 128) {
        float s = redS[tid][0] + redS[tid][1] + redS[tid][2] + redS[tid][3];
        g_part[((size_t)bh * S + q0 + tid) * KT + blockIdx.x] = s;
    }
}

// ---------------------------------------------------------------------------
// Kernel 3: combine per-row tile partials -> 1/sum
// ---------------------------------------------------------------------------
__global__ __launch_bounds__(256) void combine_kernel()
{
    using namespace cfg;
    int row = blockIdx.x * 256 + threadIdx.x;
    const float* p = &g_part[(size_t)row * KT];
    float s = 0.0f;
#pragma unroll
    for (int i = 0; i < KT; i++) s += p[i];
    g_stats[row] = 1.0f / s;
}

// ---------------------------------------------------------------------------
// Kernel 4: fused softmax-apply + P@V, 3-term split-bf16 (h is checked
// per-tensor at 1e-3: plain bf16 measured 1.8e-3, split gives ~2e-5).
// Tile 128(q) x 64(w), BK=32, reg-prefetch.
// ---------------------------------------------------------------------------
__global__ __launch_bounds__(256, 2) void pv_kernel(
    const float* __restrict__ scores, float* __restrict__ soft,
    float* __restrict__ out_h)
{
    using namespace cfg;
    const int bh = blockIdx.y;
    const int b  = bh >> 4, hd = bh & 15;
    const int q0 = blockIdx.x * 128;

    __shared__ __align__(16) uint32_t sPh[128][20], sPl[128][20];
    __shared__ __align__(16) uint32_t sVh[16][72],  sVl[16][72];   // [k2][w]
    __shared__ float sInv[128];

    const int tid = threadIdx.x;
    const int lane = tid & 31, wid = tid >> 5;
    const int g = lane >> 2, t = lane & 3;
    const int wm = wid & 3, wn = wid >> 2;

    const float* Pbase = scores + ((size_t)bh * S + q0) * S;
    float* Sbase = soft + ((size_t)bh * S + q0) * S;
    const size_t vpair0 = (size_t)(b * S) / 2;

    if (tid < 128) sInv[tid] = g_stats[(size_t)bh * S + q0 + tid];
    __syncthreads();

    float acc[2][4][4] = {};
    float4 pr[4];
    uint4 rv[2];

    auto load_v = [&](int k0) {
#pragma unroll
        for (int p = 0; p < 2; p++) {
            int idx = tid & 255;
            int k2 = idx >> 4, ch = idx & 15;
            const uint32_t* src = p ? g_Vpl : g_Vph;
            rv[p] = *reinterpret_cast<const uint4*>(
                &src[(vpair0 + (k0 >> 1) + k2) * D + hd * W + ch * 4]);
        }
    };
    auto load_p = [&](int k0) {
#pragma unroll
        for (int p = 0; p < 4; p++) {
            int idx = tid + 256 * p;
            int row = idx >> 3;
            int c4  = (idx & 7) * 4;
            pr[p] = *reinterpret_cast<const float4*>(&Pbase[(size_t)row * S + k0 + c4]);
        }
    };

    load_p(0);
    load_v(0);

    for (int k0 = 0; k0 < S; k0 += 32) {
        // exp + write soft + split into smem
#pragma unroll
        for (int p = 0; p < 4; p++) {
            int idx = tid + 256 * p;
            int row = idx >> 3;
            int c4  = (idx & 7) * 4;
            float inv = sInv[row];
            float e0 = __expf(pr[p].x) * inv;
            float e1 = __expf(pr[p].y) * inv;
            float e2 = __expf(pr[p].z) * inv;
            float e3 = __expf(pr[p].w) * inv;
            *reinterpret_cast<float4*>(&Sbase[(size_t)row * S + k0 + c4]) =
                make_float4(e0, e1, e2, e3);
            uint32_t h0, l0, h1, l1;
            splitpair(e0, e1, h0, l0);
            splitpair(e2, e3, h1, l1);
            *reinterpret_cast<uint2*>(&sPh[row][c4 >> 1]) = make_uint2(h0, h1);
            *reinterpret_cast<uint2*>(&sPl[row][c4 >> 1]) = make_uint2(l0, l1);
        }
        {
            int idx = tid & 255;
            int k2 = idx >> 4, ch = idx & 15;
            *reinterpret_cast<uint4*>(&sVh[k2][ch * 4]) = rv[0];
            *reinterpret_cast<uint4*>(&sVl[k2][ch * 4]) = rv[1];
        }
        __syncthreads();

        if (k0 + 32 < S) {
            load_p(k0 + 32);
            load_v(k0 + 32);
        }

#pragma unroll
        for (int ka = 0; ka < 2; ka++) {
            uint32_t bh_[4][2], bl_[4][2];
#pragma unroll
            for (int na = 0; na < 4; na++) {
                int n = wn * 32 + na * 8 + g;
                bh_[na][0] = sVh[ka * 8 + t][n];
                bh_[na][1] = sVh[ka * 8 + t + 4][n];
                bl_[na][0] = sVl[ka * 8 + t][n];
                bl_[na][1] = sVl[ka * 8 + t + 4][n];
            }
#pragma unroll
            for (int ma = 0; ma < 2; ma++) {
                int r = wm * 32 + ma * 16 + g;
                int c = ka * 8 + t;
                uint32_t ah0 = sPh[r][c],     ah1 = sPh[r + 8][c];
                uint32_t ah2 = sPh[r][c + 4], ah3 = sPh[r + 8][c + 4];
                uint32_t al0 = sPl[r][c],     al1 = sPl[r + 8][c];
                uint32_t al2 = sPl[r][c + 4], al3 = sPl[r + 8][c + 4];
#pragma unroll
                for (int na = 0; na < 4; na++) {
                    float* d = acc[ma][na];
                    bmma(d[0], d[1], d[2], d[3], ah0, ah1, ah2, ah3, bh_[na][0], bh_[na][1]);
                    bmma(d[0], d[1], d[2], d[3], ah0, ah1, ah2, ah3, bl_[na][0], bl_[na][1]);
                    bmma(d[0], d[1], d[2], d[3], al0, al1, al2, al3, bh_[na][0], bh_[na][1]);
                }
            }
        }
        __syncthreads();
    }

#pragma unroll
    for (int ma = 0; ma < 2; ma++) {
#pragma unroll
        for (int na = 0; na < 4; na++) {
            int rowl = wm * 32 + ma * 16 + g;
            int coll = wn * 32 + na * 8 + 2 * t;
            float* d = acc[ma][na];
            size_t base = (size_t)(b * S + q0 + rowl) * D + hd * W + coll;
            *reinterpret_cast<float2*>(&out_h[base]) = make_float2(d[0], d[1]);
            *reinterpret_cast<float2*>(&out_h[base + (size_t)8 * D]) = make_float2(d[2], d[3]);
        }
    }
}

// ---------------------------------------------------------------------------
// Launch. d_out layout: [h | scores_soft | scores], fp32.
// ---------------------------------------------------------------------------
extern "C" void kernel_launch(void* const* d_in, const int* in_sizes, int n_in,
                              void* d_out, int out_size)
{
    using namespace cfg;
    (void)in_sizes; (void)n_in; (void)out_size;
    const float* x    = (const float*)d_in[0];
    const float* mask = (const float*)d_in[1];
    const float* wq   = (const float*)d_in[2];
    const float* bq   = (const float*)d_in[3];
    const float* wk   = (const float*)d_in[4];
    const float* bk   = (const float*)d_in[5];
    const float* wv   = (const float*)d_in[6];
    const float* bv   = (const float*)d_in[7];

    float* out   = (float*)d_out;
    float* out_h = out;
    float* out_p = out + H_ELEMS;              // scores_soft
    float* out_s = out + H_ELEMS + P_ELEMS;    // raw scores

    split_x_kernel<<<M * D / 4 / 256, 256>>>(x);
    {
        dim3 grid((D / 2) * D / 256, 1, 3);
        pack_w_kernel<<<grid, 256>>>(wq, wk, wv);
    }
    {
        dim3 grid(D / 128, M / 128, 3);
        qkv_gemm_kernel<<<grid, 256>>>(bq, bk, bv);
    }
    repack_v_kernel<<<(M / 2) * (D / 2) / 256, 256>>>();
    {
        dim3 grid(S / 128, S / 128, B * H);
        scores_kernel<<<grid, 256>>>(mask, out_s);
    }
    combine_kernel<<<ROWS / 256, 256>>>();
    {
        dim3 grid(S / 128, B * H);
        pv_kernel<<<grid, 256>>>(out_s, out_p, out_h);
    }
}

// round 10
// speedup vs baseline: 2.6674x; 1.0843x over previous
#include <cuda_runtime.h>
#include <cuda_bf16.h>
#include <cstdint>

// Problem constants
namespace cfg {
constexpr int B = 2, S = 2048, D = 1024, H = 16, W = 64;
constexpr int M = B * S;                                  // 4096
constexpr int ROWS = B * H * S;                           // 65536 score rows
constexpr int KT = S / 128;                               // 16 k-tiles per row
constexpr long long H_ELEMS = (long long)B * S * D;       // 4,194,304
constexpr long long P_ELEMS = (long long)B * H * S * S;   // 134,217,728
}

// Scratch: split-bf16 operands, packed weights/V, softmax partials.
__device__ __nv_bfloat16 g_xh[cfg::M * cfg::D], g_xl[cfg::M * cfg::D];
__device__ __nv_bfloat16 g_Qh[cfg::M * cfg::D], g_Ql[cfg::M * cfg::D];
__device__ __nv_bfloat16 g_Kh[cfg::M * cfg::D], g_Kl[cfg::M * cfg::D];
__device__ __nv_bfloat16 g_Vh[cfg::M * cfg::D], g_Vl[cfg::M * cfg::D];
__device__ uint32_t g_Wph[3][(cfg::D / 2) * cfg::D];   // pair-packed weights (hi)
__device__ uint32_t g_Wpl[3][(cfg::D / 2) * cfg::D];   // (lo)
__device__ uint32_t g_Vph[(cfg::M / 2) * cfg::D];      // pair-packed V (hi)
__device__ uint32_t g_Vpl[(cfg::M / 2) * cfg::D];      // (lo)
__device__ float g_part[cfg::ROWS * cfg::KT];    // per (row, ktile): sumexp
__device__ float g_stats[cfg::ROWS];             // per row: 1/sum

// ---------------------------------------------------------------------------
// Helpers
// ---------------------------------------------------------------------------
__device__ __forceinline__ void splitone(float x, unsigned short& h, unsigned short& l)
{
    __nv_bfloat16 hb = __float2bfloat16(x);
    __nv_bfloat16 lb = __float2bfloat16(x - __bfloat162float(hb));
    h = __bfloat16_as_ushort(hb);
    l = __bfloat16_as_ushort(lb);
}

__device__ __forceinline__ void splitpair(float x0, float x1,
                                          uint32_t& hi, uint32_t& lo)
{
    unsigned short h0, l0, h1, l1;
    splitone(x0, h0, l0);
    splitone(x1, h1, l1);
    hi = ((uint32_t)h1 << 16) | h0;
    lo = ((uint32_t)l1 << 16) | l0;
}

__device__ __forceinline__ void bmma(float& d0, float& d1, float& d2, float& d3,
                                     uint32_t a0, uint32_t a1, uint32_t a2, uint32_t a3,
                                     uint32_t b0, uint32_t b1)
{
    asm volatile(
        "mma.sync.aligned.m16n8k16.row.col.f32.bf16.bf16.f32 "
        "{%0,%1,%2,%3},{%4,%5,%6,%7},{%8,%9},{%0,%1,%2,%3};\n"
        : "+f"(d0), "+f"(d1), "+f"(d2), "+f"(d3)
        : "r"(a0), "r"(a1), "r"(a2), "r"(a3), "r"(b0), "r"(b1));
}

// ---------------------------------------------------------------------------
// Prep 1: split x into hi/lo bf16.
// ---------------------------------------------------------------------------
__global__ __launch_bounds__(256) void split_x_kernel(const float* __restrict__ x)
{
    int i = blockIdx.x * 256 + threadIdx.x;
    float4 v = reinterpret_cast<const float4*>(x)[i];
    ushort4 hv, lv;
    splitone(v.x, hv.x, lv.x);
    splitone(v.y, hv.y, lv.y);
    splitone(v.z, hv.z, lv.z);
    splitone(v.w, hv.w, lv.w);
    reinterpret_cast<ushort4*>(g_xh)[i] = hv;
    reinterpret_cast<ushort4*>(g_xl)[i] = lv;
}

// ---------------------------------------------------------------------------
// Prep 2: pair-pack weights along k.
// ---------------------------------------------------------------------------
__global__ __launch_bounds__(256) void pack_w_kernel(
    const float* __restrict__ wq, const float* __restrict__ wk,
    const float* __restrict__ wv)
{
    using namespace cfg;
    const int z = blockIdx.z;
    const float* w = (z == 0) ? wq : (z == 1) ? wk : wv;
    int idx = blockIdx.x * 256 + threadIdx.x;
    int k2 = idx >> 10, n = idx & 1023;
    float v0 = w[(size_t)(2 * k2) * D + n];
    float v1 = w[(size_t)(2 * k2 + 1) * D + n];
    uint32_t h, l;
    splitpair(v0, v1, h, l);
    g_Wph[z][idx] = h;
    g_Wpl[z][idx] = l;
}

// ---------------------------------------------------------------------------
// Prep 3 (after qkv): pair-pack V (hi+lo) along kpos.
// ---------------------------------------------------------------------------
__global__ __launch_bounds__(256) void repack_v_kernel()
{
    using namespace cfg;
    int idx = blockIdx.x * 256 + threadIdx.x;    // M/2 * D/2, 2 d each
    int p  = idx >> 9;
    int d2 = (idx & 511) * 2;
    uint32_t ah = *reinterpret_cast<const uint32_t*>(&g_Vh[(size_t)(2 * p) * D + d2]);
    uint32_t bh_ = *reinterpret_cast<const uint32_t*>(&g_Vh[(size_t)(2 * p + 1) * D + d2]);
    uint32_t al = *reinterpret_cast<const uint32_t*>(&g_Vl[(size_t)(2 * p) * D + d2]);
    uint32_t bl = *reinterpret_cast<const uint32_t*>(&g_Vl[(size_t)(2 * p + 1) * D + d2]);
    uint2 oh, ol;
    oh.x = __byte_perm(ah, bh_, 0x5410);
    oh.y = __byte_perm(ah, bh_, 0x7632);
    ol.x = __byte_perm(al, bl, 0x5410);
    ol.y = __byte_perm(al, bl, 0x7632);
    *reinterpret_cast<uint2*>(&g_Vph[(size_t)p * D + d2]) = oh;
    *reinterpret_cast<uint2*>(&g_Vpl[(size_t)p * D + d2]) = ol;
}

// ---------------------------------------------------------------------------
// Kernel 1: QKV projection, double-buffered smem (1 sync per k-iteration).
// Dynamic smem: 2 buffers x (A hi/lo [128][20] + B hi/lo [16][136]).
// ---------------------------------------------------------------------------
namespace qdims {
constexpr int A_SZ = 128 * 20;        // u32 per A array
constexpr int B_SZ = 16 * 136;        // u32 per B array
constexpr int BUF  = 2 * A_SZ + 2 * B_SZ;   // 9472 u32 per buffer
constexpr int SMEM_BYTES = 2 * BUF * 4;     // 75776 B
}

__global__ __launch_bounds__(256) void qkv_gemm_kernel(
    const float* __restrict__ bq, const float* __restrict__ bk,
    const float* __restrict__ bv)
{
    using namespace cfg;
    using namespace qdims;
    const int z = blockIdx.z;
    const float* bias = (z == 0) ? bq : (z == 1) ? bk : bv;
    __nv_bfloat16* oh = (z == 0) ? g_Qh : (z == 1) ? g_Kh : g_Vh;
    __nv_bfloat16* ol = (z == 0) ? g_Ql : (z == 1) ? g_Kl : g_Vl;
    const uint32_t* wph = g_Wph[z];
    const uint32_t* wpl = g_Wpl[z];

    extern __shared__ __align__(16) uint32_t dyn[];

    const int tid = threadIdx.x;
    const int lane = tid & 31, wid = tid >> 5;
    const int g = lane >> 2, t = lane & 3;
    const int wm = wid & 1, wn = wid >> 1;
    const int m0 = blockIdx.y * 128;
    const int n0 = blockIdx.x * 128;

    float acc[4][4][4] = {};
    uint4 ra[4], rb[4];

    auto load_regs = [&](int k0) {
#pragma unroll
        for (int p = 0; p < 4; p++) {
            int idx = tid + 256 * p;
            int rem = idx & 511;
            const __nv_bfloat16* src = (p >> 1) ? g_xl : g_xh;
            int row = rem >> 2, ch = rem & 3;
            ra[p] = *reinterpret_cast<const uint4*>(
                &src[(size_t)(m0 + row) * D + k0 + ch * 8]);
        }
#pragma unroll
        for (int p = 0; p < 4; p++) {
            int idx = tid + 256 * p;
            int rem = idx & 511;
            const uint32_t* src = (p >> 1) ? wpl : wph;
            int k2 = rem >> 5, ch = rem & 31;
            rb[p] = *reinterpret_cast<const uint4*>(
                &src[(size_t)((k0 >> 1) + k2) * D + n0 + ch * 4]);
        }
    };
    auto store_smem = [&](int buf) {
        uint32_t* base = dyn + buf * BUF;
#pragma unroll
        for (int p = 0; p < 4; p++) {
            int idx = tid + 256 * p;
            int rem = idx & 511;
            int row = rem >> 2, ch = rem & 3;
            uint32_t* dst = base + ((p >> 1) ? A_SZ : 0);
            *reinterpret_cast<uint4*>(&dst[row * 20 + ch * 4]) = ra[p];
        }
#pragma unroll
        for (int p = 0; p < 4; p++) {
            int idx = tid + 256 * p;
            int rem = idx & 511;
            int k2 = rem >> 5, ch = rem & 31;
            uint32_t* dst = base + 2 * A_SZ + ((p >> 1) ? B_SZ : 0);
            *reinterpret_cast<uint4*>(&dst[k2 * 136 + ch * 4]) = rb[p];
        }
    };

    load_regs(0);
    store_smem(0);
    __syncthreads();

    for (int ks = 0; ks < D / 32; ks++) {
        if (ks + 1 < D / 32) load_regs((ks + 1) * 32);

        const uint32_t* base = dyn + (ks & 1) * BUF;
        const uint32_t* sAh = base;
        const uint32_t* sAl = base + A_SZ;
        const uint32_t* sBh = base + 2 * A_SZ;
        const uint32_t* sBl = base + 2 * A_SZ + B_SZ;

#pragma unroll
        for (int ka = 0; ka < 2; ka++) {
            uint32_t bh[4][2], bl[4][2];
#pragma unroll
            for (int na = 0; na < 4; na++) {
                int n = wn * 32 + na * 8 + g;
                bh[na][0] = sBh[(ka * 8 + t) * 136 + n];
                bh[na][1] = sBh[(ka * 8 + t + 4) * 136 + n];
                bl[na][0] = sBl[(ka * 8 + t) * 136 + n];
                bl[na][1] = sBl[(ka * 8 + t + 4) * 136 + n];
            }
#pragma unroll
            for (int ma = 0; ma < 4; ma++) {
                int r = wm * 64 + ma * 16 + g;
                int c = ka * 8 + t;
                uint32_t ah0 = sAh[r * 20 + c],       ah1 = sAh[(r + 8) * 20 + c];
                uint32_t ah2 = sAh[r * 20 + c + 4],   ah3 = sAh[(r + 8) * 20 + c + 4];
                uint32_t al0 = sAl[r * 20 + c],       al1 = sAl[(r + 8) * 20 + c];
                uint32_t al2 = sAl[r * 20 + c + 4],   al3 = sAl[(r + 8) * 20 + c + 4];
#pragma unroll
                for (int na = 0; na < 4; na++) {
                    float* d = acc[ma][na];
                    bmma(d[0], d[1], d[2], d[3], ah0, ah1, ah2, ah3, bh[na][0], bh[na][1]);
                    bmma(d[0], d[1], d[2], d[3], ah0, ah1, ah2, ah3, bl[na][0], bl[na][1]);
                    bmma(d[0], d[1], d[2], d[3], al0, al1, al2, al3, bh[na][0], bh[na][1]);
                }
            }
        }

        if (ks + 1 < D / 32) store_smem((ks + 1) & 1);
        __syncthreads();
    }

#pragma unroll
    for (int ma = 0; ma < 4; ma++) {
#pragma unroll
        for (int na = 0; na < 4; na++) {
            int row = m0 + wm * 64 + ma * 16 + g;
            int col = n0 + wn * 32 + na * 8 + 2 * t;
            float b0 = bias[col], b1 = bias[col + 1];
            float* d = acc[ma][na];
            float v0 = d[0] + b0, v1 = d[1] + b1;
            float v2 = d[2] + b0, v3 = d[3] + b1;
            ushort2 hv, lv;
            splitone(v0, hv.x, lv.x);
            splitone(v1, hv.y, lv.y);
            *reinterpret_cast<ushort2*>(&oh[(size_t)row * D + col]) = hv;
            *reinterpret_cast<ushort2*>(&ol[(size_t)row * D + col]) = lv;
            splitone(v2, hv.x, lv.x);
            splitone(v3, hv.y, lv.y);
            *reinterpret_cast<ushort2*>(&oh[(size_t)(row + 8) * D + col]) = hv;
            *reinterpret_cast<ushort2*>(&ol[(size_t)(row + 8) * D + col]) = lv;
        }
    }
}

// ---------------------------------------------------------------------------
// Kernel 2: scores = Q Kt / 8 - 10000*(1-mask) + sumexp partials.
// Full K=64 in smem at once: ONE sync, then 192 MMAs with no barriers.
// Dynamic smem: 4 arrays [128][36] u32 + redS.
// ---------------------------------------------------------------------------
namespace sdims {
constexpr int ARR = 128 * 36;                 // u32 per array
constexpr int SMEM_BYTES = 4 * ARR * 4 + 128 * 4 * 4;   // 73728 + 2048
}

__global__ __launch_bounds__(256) void scores_kernel(
    const float* __restrict__ mask, float* __restrict__ out_s)
{
    using namespace cfg;
    using namespace sdims;
    const int bh = blockIdx.z;
    const int b  = bh >> 4, hd = bh & 15;
    const int q0 = blockIdx.y * 128;
    const int k0 = blockIdx.x * 128;

    extern __shared__ __align__(16) uint32_t dyn[];
    uint32_t* sQh = dyn;
    uint32_t* sQl = dyn + ARR;
    uint32_t* sKh = dyn + 2 * ARR;
    uint32_t* sKl = dyn + 3 * ARR;
    float* redS = reinterpret_cast<float*>(dyn + 4 * ARR);   // [128][4]

    const int tid = threadIdx.x;
    const int lane = tid & 31, wid = tid >> 5;
    const int g = lane >> 2, t = lane & 3;
    const int wm = wid & 1, wn = wid >> 1;

    const __nv_bfloat16* gQh = g_Qh + (size_t)(b * S + q0) * D + hd * W;
    const __nv_bfloat16* gQl = g_Ql + (size_t)(b * S + q0) * D + hd * W;
    const __nv_bfloat16* gKh = g_Kh + (size_t)(b * S + k0) * D + hd * W;
    const __nv_bfloat16* gKl = g_Kl + (size_t)(b * S + k0) * D + hd * W;

    // Load all Q/K hi/lo tiles (full 64-wide) into smem. 4 uint4 per array.
    {
        const int row = tid >> 3, ch = tid & 7;   // covers 32 rows per pass
#pragma unroll
        for (int p = 0; p < 4; p++) {
            int r = row + 32 * p;
            size_t go = (size_t)r * D + ch * 8;
            *reinterpret_cast<uint4*>(&sQh[r * 36 + ch * 4]) =
                *reinterpret_cast<const uint4*>(&gQh[go]);
            *reinterpret_cast<uint4*>(&sQl[r * 36 + ch * 4]) =
                *reinterpret_cast<const uint4*>(&gQl[go]);
            *reinterpret_cast<uint4*>(&sKh[r * 36 + ch * 4]) =
                *reinterpret_cast<const uint4*>(&gKh[go]);
            *reinterpret_cast<uint4*>(&sKl[r * 36 + ch * 4]) =
                *reinterpret_cast<const uint4*>(&gKl[go]);
        }
    }
    __syncthreads();

    float acc[4][4][4] = {};

#pragma unroll
    for (int ka = 0; ka < 4; ka++) {
        uint32_t bh_[4][2], bl_[4][2];
#pragma unroll
        for (int na = 0; na < 4; na++) {
            int n = wn * 32 + na * 8 + g;
            bh_[na][0] = sKh[n * 36 + ka * 8 + t];
            bh_[na][1] = sKh[n * 36 + ka * 8 + t + 4];
            bl_[na][0] = sKl[n * 36 + ka * 8 + t];
            bl_[na][1] = sKl[n * 36 + ka * 8 + t + 4];
        }
#pragma unroll
        for (int ma = 0; ma < 4; ma++) {
            int r = wm * 64 + ma * 16 + g;
            int c = ka * 8 + t;
            uint32_t ah0 = sQh[r * 36 + c],       ah1 = sQh[(r + 8) * 36 + c];
            uint32_t ah2 = sQh[r * 36 + c + 4],   ah3 = sQh[(r + 8) * 36 + c + 4];
            uint32_t al0 = sQl[r * 36 + c],       al1 = sQl[(r + 8) * 36 + c];
            uint32_t al2 = sQl[r * 36 + c + 4],   al3 = sQl[(r + 8) * 36 + c + 4];
#pragma unroll
            for (int na = 0; na < 4; na++) {
                float* d = acc[ma][na];
                bmma(d[0], d[1], d[2], d[3], ah0, ah1, ah2, ah3, bh_[na][0], bh_[na][1]);
                bmma(d[0], d[1], d[2], d[3], ah0, ah1, ah2, ah3, bl_[na][0], bl_[na][1]);
                bmma(d[0], d[1], d[2], d[3], al0, al1, al2, al3, bh_[na][0], bh_[na][1]);
            }
        }
    }

    // Scale + mask, store scores, accumulate sumexp partials (no max).
    const float scale = 0.125f;
    float* dst = out_s + ((size_t)bh * S + q0) * S + k0;
    float se[4][2] = {};

#pragma unroll
    for (int ma = 0; ma < 4; ma++) {
#pragma unroll
        for (int na = 0; na < 4; na++) {
            int rowl = wm * 64 + ma * 16 + g;
            int coll = wn * 32 + na * 8 + 2 * t;
            float m0v = mask[b * S + k0 + coll];
            float m1v = mask[b * S + k0 + coll + 1];
            float a0 = -10000.0f * (1.0f - m0v);
            float a1 = -10000.0f * (1.0f - m1v);
            float* d = acc[ma][na];
            float v0 = d[0] * scale + a0, v1 = d[1] * scale + a1;
            float v2 = d[2] * scale + a0, v3 = d[3] * scale + a1;
            *reinterpret_cast<float2*>(&dst[(size_t)rowl * S + coll]) = make_float2(v0, v1);
            *reinterpret_cast<float2*>(&dst[(size_t)(rowl + 8) * S + coll]) = make_float2(v2, v3);
            se[ma][0] += __expf(v0) + __expf(v1);
            se[ma][1] += __expf(v2) + __expf(v3);
        }
    }
#pragma unroll
    for (int ma = 0; ma < 4; ma++)
#pragma unroll
        for (int hf = 0; hf < 2; hf++) {
            float s = se[ma][hf];
            s += __shfl_xor_sync(0xffffffffu, s, 1);
            s += __shfl_xor_sync(0xffffffffu, s, 2);
            se[ma][hf] = s;
        }
    if (t == 0) {
#pragma unroll
        for (int ma = 0; ma < 4; ma++)
#pragma unroll
            for (int hf = 0; hf < 2; hf++)
                redS[(wm * 64 + ma * 16 + g + hf * 8) * 4 + wn] = se[ma][hf];
    }
    __syncthreads();

    if (tid < 128) {
        float s = redS[tid * 4 + 0] + redS[tid * 4 + 1]
                + redS[tid * 4 + 2] + redS[tid * 4 + 3];
        g_part[((size_t)bh * S + q0 + tid) * KT + blockIdx.x] = s;
    }
}

// ---------------------------------------------------------------------------
// Kernel 3: combine per-row tile partials -> 1/sum
// ---------------------------------------------------------------------------
__global__ __launch_bounds__(256) void combine_kernel()
{
    using namespace cfg;
    int row = blockIdx.x * 256 + threadIdx.x;
    const float* p = &g_part[(size_t)row * KT];
    float s = 0.0f;
#pragma unroll
    for (int i = 0; i < KT; i++) s += p[i];
    g_stats[row] = 1.0f / s;
}

// ---------------------------------------------------------------------------
// Kernel 4: fused softmax-apply + P@V, 3-term split-bf16.
// Tile 128(q) x 64(w), BK=32, reg-prefetch. (Near memory floor — unchanged.)
// ---------------------------------------------------------------------------
__global__ __launch_bounds__(256, 2) void pv_kernel(
    const float* __restrict__ scores, float* __restrict__ soft,
    float* __restrict__ out_h)
{
    using namespace cfg;
    const int bh = blockIdx.y;
    const int b  = bh >> 4, hd = bh & 15;
    const int q0 = blockIdx.x * 128;

    __shared__ __align__(16) uint32_t sPh[128][20], sPl[128][20];
    __shared__ __align__(16) uint32_t sVh[16][72],  sVl[16][72];   // [k2][w]
    __shared__ float sInv[128];

    const int tid = threadIdx.x;
    const int lane = tid & 31, wid = tid >> 5;
    const int g = lane >> 2, t = lane & 3;
    const int wm = wid & 3, wn = wid >> 2;

    const float* Pbase = scores + ((size_t)bh * S + q0) * S;
    float* Sbase = soft + ((size_t)bh * S + q0) * S;
    const size_t vpair0 = (size_t)(b * S) / 2;

    if (tid < 128) sInv[tid] = g_stats[(size_t)bh * S + q0 + tid];
    __syncthreads();

    float acc[2][4][4] = {};
    float4 pr[4];
    uint4 rv[2];

    auto load_v = [&](int k0) {
#pragma unroll
        for (int p = 0; p < 2; p++) {
            int idx = tid & 255;
            int k2 = idx >> 4, ch = idx & 15;
            const uint32_t* src = p ? g_Vpl : g_Vph;
            rv[p] = *reinterpret_cast<const uint4*>(
                &src[(vpair0 + (k0 >> 1) + k2) * D + hd * W + ch * 4]);
        }
    };
    auto load_p = [&](int k0) {
#pragma unroll
        for (int p = 0; p < 4; p++) {
            int idx = tid + 256 * p;
            int row = idx >> 3;
            int c4  = (idx & 7) * 4;
            pr[p] = *reinterpret_cast<const float4*>(&Pbase[(size_t)row * S + k0 + c4]);
        }
    };

    load_p(0);
    load_v(0);

    for (int k0 = 0; k0 < S; k0 += 32) {
        // exp + write soft + split into smem
#pragma unroll
        for (int p = 0; p < 4; p++) {
            int idx = tid + 256 * p;
            int row = idx >> 3;
            int c4  = (idx & 7) * 4;
            float inv = sInv[row];
            float e0 = __expf(pr[p].x) * inv;
            float e1 = __expf(pr[p].y) * inv;
            float e2 = __expf(pr[p].z) * inv;
            float e3 = __expf(pr[p].w) * inv;
            *reinterpret_cast<float4*>(&Sbase[(size_t)row * S + k0 + c4]) =
                make_float4(e0, e1, e2, e3);
            uint32_t h0, l0, h1, l1;
            splitpair(e0, e1, h0, l0);
            splitpair(e2, e3, h1, l1);
            *reinterpret_cast<uint2*>(&sPh[row][c4 >> 1]) = make_uint2(h0, h1);
            *reinterpret_cast<uint2*>(&sPl[row][c4 >> 1]) = make_uint2(l0, l1);
        }
        {
            int idx = tid & 255;
            int k2 = idx >> 4, ch = idx & 15;
            *reinterpret_cast<uint4*>(&sVh[k2][ch * 4]) = rv[0];
            *reinterpret_cast<uint4*>(&sVl[k2][ch * 4]) = rv[1];
        }
        __syncthreads();

        if (k0 + 32 < S) {
            load_p(k0 + 32);
            load_v(k0 + 32);
        }

#pragma unroll
        for (int ka = 0; ka < 2; ka++) {
            uint32_t bh_[4][2], bl_[4][2];
#pragma unroll
            for (int na = 0; na < 4; na++) {
                int n = wn * 32 + na * 8 + g;
                bh_[na][0] = sVh[ka * 8 + t][n];
                bh_[na][1] = sVh[ka * 8 + t + 4][n];
                bl_[na][0] = sVl[ka * 8 + t][n];
                bl_[na][1] = sVl[ka * 8 + t + 4][n];
            }
#pragma unroll
            for (int ma = 0; ma < 2; ma++) {
                int r = wm * 32 + ma * 16 + g;
                int c = ka * 8 + t;
                uint32_t ah0 = sPh[r][c],     ah1 = sPh[r + 8][c];
                uint32_t ah2 = sPh[r][c + 4], ah3 = sPh[r + 8][c + 4];
                uint32_t al0 = sPl[r][c],     al1 = sPl[r + 8][c];
                uint32_t al2 = sPl[r][c + 4], al3 = sPl[r + 8][c + 4];
#pragma unroll
                for (int na = 0; na < 4; na++) {
                    float* d = acc[ma][na];
                    bmma(d[0], d[1], d[2], d[3], ah0, ah1, ah2, ah3, bh_[na][0], bh_[na][1]);
                    bmma(d[0], d[1], d[2], d[3], ah0, ah1, ah2, ah3, bl_[na][0], bl_[na][1]);
                    bmma(d[0], d[1], d[2], d[3], al0, al1, al2, al3, bh_[na][0], bh_[na][1]);
                }
            }
        }
        __syncthreads();
    }

#pragma unroll
    for (int ma = 0; ma < 2; ma++) {
#pragma unroll
        for (int na = 0; na < 4; na++) {
            int rowl = wm * 32 + ma * 16 + g;
            int coll = wn * 32 + na * 8 + 2 * t;
            float* d = acc[ma][na];
            size_t base = (size_t)(b * S + q0 + rowl) * D + hd * W + coll;
            *reinterpret_cast<float2*>(&out_h[base]) = make_float2(d[0], d[1]);
            *reinterpret_cast<float2*>(&out_h[base + (size_t)8 * D]) = make_float2(d[2], d[3]);
        }
    }
}

// ---------------------------------------------------------------------------
// Launch. d_out layout: [h | scores_soft | scores], fp32.
// ---------------------------------------------------------------------------
extern "C" void kernel_launch(void* const* d_in, const int* in_sizes, int n_in,
                              void* d_out, int out_size)
{
    using namespace cfg;
    (void)in_sizes; (void)n_in; (void)out_size;
    const float* x    = (const float*)d_in[0];
    const float* mask = (const float*)d_in[1];
    const float* wq   = (const float*)d_in[2];
    const float* bq   = (const float*)d_in[3];
    const float* wk   = (const float*)d_in[4];
    const float* bk   = (const float*)d_in[5];
    const float* wv   = (const float*)d_in[6];
    const float* bv   = (const float*)d_in[7];

    float* out   = (float*)d_out;
    float* out_h = out;
    float* out_p = out + H_ELEMS;              // scores_soft
    float* out_s = out + H_ELEMS + P_ELEMS;    // raw scores

    // Opt-in to >48KB dynamic smem (idempotent, not a stream op: capture-safe).
    cudaFuncSetAttribute(qkv_gemm_kernel,
                         cudaFuncAttributeMaxDynamicSharedMemorySize,
                         qdims::SMEM_BYTES);
    cudaFuncSetAttribute(scores_kernel,
                         cudaFuncAttributeMaxDynamicSharedMemorySize,
                         sdims::SMEM_BYTES);

    split_x_kernel<<<M * D / 4 / 256, 256>>>(x);
    {
        dim3 grid((D / 2) * D / 256, 1, 3);
        pack_w_kernel<<<grid, 256>>>(wq, wk, wv);
    }
    {
        dim3 grid(D / 128, M / 128, 3);
        qkv_gemm_kernel<<<grid, 256, qdims::SMEM_BYTES>>>(bq, bk, bv);
    }
    repack_v_kernel<<<(M / 2) * (D / 2) / 256, 256>>>();
    {
        dim3 grid(S / 128, S / 128, B * H);
        scores_kernel<<<grid, 256, sdims::SMEM_BYTES>>>(mask, out_s);
    }
    combine_kernel<<<ROWS / 256, 256>>>();
    {
        dim3 grid(S / 128, B * H);
        pv_kernel<<<grid, 256>>>(out_s, out_p, out_h);
    }
}

// round 17
// speedup vs baseline: 2.6706x; 1.0012x over previous
#include <cuda_runtime.h>
#include <cuda_bf16.h>
#include <cstdint>

// Problem constants
namespace cfg {
constexpr int B = 2, S = 2048, D = 1024, H = 16, W = 64;
constexpr int M = B * S;                                  // 4096
constexpr int ROWS = B * H * S;                           // 65536 score rows
constexpr int KT = S / 128;                               // 16 k-tiles per row
constexpr long long H_ELEMS = (long long)B * S * D;       // 4,194,304
constexpr long long P_ELEMS = (long long)B * H * S * S;   // 134,217,728
}

// Scratch: split-bf16 operands, packed weights/V, softmax partials.
__device__ __nv_bfloat16 g_xh[cfg::M * cfg::D], g_xl[cfg::M * cfg::D];
__device__ __nv_bfloat16 g_Qh[cfg::M * cfg::D], g_Ql[cfg::M * cfg::D];
__device__ __nv_bfloat16 g_Kh[cfg::M * cfg::D], g_Kl[cfg::M * cfg::D];
__device__ __nv_bfloat16 g_Vh[cfg::M * cfg::D], g_Vl[cfg::M * cfg::D];
__device__ uint32_t g_Wph[3][(cfg::D / 2) * cfg::D];   // pair-packed weights (hi)
__device__ uint32_t g_Wpl[3][(cfg::D / 2) * cfg::D];   // (lo)
__device__ uint32_t g_Vph[(cfg::M / 2) * cfg::D];      // pair-packed V (hi)
__device__ uint32_t g_Vpl[(cfg::M / 2) * cfg::D];      // (lo)
__device__ float g_part[cfg::ROWS * cfg::KT];    // per (row, ktile): sumexp

// ---------------------------------------------------------------------------
// Helpers
// ---------------------------------------------------------------------------
__device__ __forceinline__ void splitone(float x, unsigned short& h, unsigned short& l)
{
    __nv_bfloat16 hb = __float2bfloat16(x);
    __nv_bfloat16 lb = __float2bfloat16(x - __bfloat162float(hb));
    h = __bfloat16_as_ushort(hb);
    l = __bfloat16_as_ushort(lb);
}

__device__ __forceinline__ void splitpair(float x0, float x1,
                                          uint32_t& hi, uint32_t& lo)
{
    unsigned short h0, l0, h1, l1;
    splitone(x0, h0, l0);
    splitone(x1, h1, l1);
    hi = ((uint32_t)h1 << 16) | h0;
    lo = ((uint32_t)l1 << 16) | l0;
}

__device__ __forceinline__ void bmma(float& d0, float& d1, float& d2, float& d3,
                                     uint32_t a0, uint32_t a1, uint32_t a2, uint32_t a3,
                                     uint32_t b0, uint32_t b1)
{
    asm volatile(
        "mma.sync.aligned.m16n8k16.row.col.f32.bf16.bf16.f32 "
        "{%0,%1,%2,%3},{%4,%5,%6,%7},{%8,%9},{%0,%1,%2,%3};\n"
        : "+f"(d0), "+f"(d1), "+f"(d2), "+f"(d3)
        : "r"(a0), "r"(a1), "r"(a2), "r"(a3), "r"(b0), "r"(b1));
}

// ---------------------------------------------------------------------------
// Prep 1: split x into hi/lo bf16.
// ---------------------------------------------------------------------------
__global__ __launch_bounds__(256) void split_x_kernel(const float* __restrict__ x)
{
    int i = blockIdx.x * 256 + threadIdx.x;
    float4 v = reinterpret_cast<const float4*>(x)[i];
    ushort4 hv, lv;
    splitone(v.x, hv.x, lv.x);
    splitone(v.y, hv.y, lv.y);
    splitone(v.z, hv.z, lv.z);
    splitone(v.w, hv.w, lv.w);
    reinterpret_cast<ushort4*>(g_xh)[i] = hv;
    reinterpret_cast<ushort4*>(g_xl)[i] = lv;
}

// ---------------------------------------------------------------------------
// Prep 2: pair-pack weights along k.
// ---------------------------------------------------------------------------
__global__ __launch_bounds__(256) void pack_w_kernel(
    const float* __restrict__ wq, const float* __restrict__ wk,
    const float* __restrict__ wv)
{
    using namespace cfg;
    const int z = blockIdx.z;
    const float* w = (z == 0) ? wq : (z == 1) ? wk : wv;
    int idx = blockIdx.x * 256 + threadIdx.x;
    int k2 = idx >> 10, n = idx & 1023;
    float v0 = w[(size_t)(2 * k2) * D + n];
    float v1 = w[(size_t)(2 * k2 + 1) * D + n];
    uint32_t h, l;
    splitpair(v0, v1, h, l);
    g_Wph[z][idx] = h;
    g_Wpl[z][idx] = l;
}

// ---------------------------------------------------------------------------
// Prep 3 (after qkv): pair-pack V (hi+lo) along kpos.
// ---------------------------------------------------------------------------
__global__ __launch_bounds__(256) void repack_v_kernel()
{
    using namespace cfg;
    int idx = blockIdx.x * 256 + threadIdx.x;    // M/2 * D/2, 2 d each
    int p  = idx >> 9;
    int d2 = (idx & 511) * 2;
    uint32_t ah = *reinterpret_cast<const uint32_t*>(&g_Vh[(size_t)(2 * p) * D + d2]);
    uint32_t bh_ = *reinterpret_cast<const uint32_t*>(&g_Vh[(size_t)(2 * p + 1) * D + d2]);
    uint32_t al = *reinterpret_cast<const uint32_t*>(&g_Vl[(size_t)(2 * p) * D + d2]);
    uint32_t bl = *reinterpret_cast<const uint32_t*>(&g_Vl[(size_t)(2 * p + 1) * D + d2]);
    uint2 oh, ol;
    oh.x = __byte_perm(ah, bh_, 0x5410);
    oh.y = __byte_perm(ah, bh_, 0x7632);
    ol.x = __byte_perm(al, bl, 0x5410);
    ol.y = __byte_perm(al, bl, 0x7632);
    *reinterpret_cast<uint2*>(&g_Vph[(size_t)p * D + d2]) = oh;
    *reinterpret_cast<uint2*>(&g_Vpl[(size_t)p * D + d2]) = ol;
}

// ---------------------------------------------------------------------------
// Kernel 1: QKV projection, double-buffered smem (1 sync per k-iteration).
// ---------------------------------------------------------------------------
namespace qdims {
constexpr int A_SZ = 128 * 20;
constexpr int B_SZ = 16 * 136;
constexpr int BUF  = 2 * A_SZ + 2 * B_SZ;
constexpr int SMEM_BYTES = 2 * BUF * 4;     // 75776 B
}

__global__ __launch_bounds__(256) void qkv_gemm_kernel(
    const float* __restrict__ bq, const float* __restrict__ bk,
    const float* __restrict__ bv)
{
    using namespace cfg;
    using namespace qdims;
    const int z = blockIdx.z;
    const float* bias = (z == 0) ? bq : (z == 1) ? bk : bv;
    __nv_bfloat16* oh = (z == 0) ? g_Qh : (z == 1) ? g_Kh : g_Vh;
    __nv_bfloat16* ol = (z == 0) ? g_Ql : (z == 1) ? g_Kl : g_Vl;
    const uint32_t* wph = g_Wph[z];
    const uint32_t* wpl = g_Wpl[z];

    extern __shared__ __align__(16) uint32_t dynq[];

    const int tid = threadIdx.x;
    const int lane = tid & 31, wid = tid >> 5;
    const int g = lane >> 2, t = lane & 3;
    const int wm = wid & 1, wn = wid >> 1;
    const int m0 = blockIdx.y * 128;
    const int n0 = blockIdx.x * 128;

    float acc[4][4][4] = {};
    uint4 ra[4], rb[4];

    auto load_regs = [&](int k0) {
#pragma unroll
        for (int p = 0; p < 4; p++) {
            int idx = tid + 256 * p;
            int rem = idx & 511;
            const __nv_bfloat16* src = (p >> 1) ? g_xl : g_xh;
            int row = rem >> 2, ch = rem & 3;
            ra[p] = *reinterpret_cast<const uint4*>(
                &src[(size_t)(m0 + row) * D + k0 + ch * 8]);
        }
#pragma unroll
        for (int p = 0; p < 4; p++) {
            int idx = tid + 256 * p;
            int rem = idx & 511;
            const uint32_t* src = (p >> 1) ? wpl : wph;
            int k2 = rem >> 5, ch = rem & 31;
            rb[p] = *reinterpret_cast<const uint4*>(
                &src[(size_t)((k0 >> 1) + k2) * D + n0 + ch * 4]);
        }
    };
    auto store_smem = [&](int buf) {
        uint32_t* base = dynq + buf * BUF;
#pragma unroll
        for (int p = 0; p < 4; p++) {
            int idx = tid + 256 * p;
            int rem = idx & 511;
            int row = rem >> 2, ch = rem & 3;
            uint32_t* dst = base + ((p >> 1) ? A_SZ : 0);
            *reinterpret_cast<uint4*>(&dst[row * 20 + ch * 4]) = ra[p];
        }
#pragma unroll
        for (int p = 0; p < 4; p++) {
            int idx = tid + 256 * p;
            int rem = idx & 511;
            int k2 = rem >> 5, ch = rem & 31;
            uint32_t* dst = base + 2 * A_SZ + ((p >> 1) ? B_SZ : 0);
            *reinterpret_cast<uint4*>(&dst[k2 * 136 + ch * 4]) = rb[p];
        }
    };

    load_regs(0);
    store_smem(0);
    __syncthreads();

    for (int ks = 0; ks < D / 32; ks++) {
        if (ks + 1 < D / 32) load_regs((ks + 1) * 32);

        const uint32_t* base = dynq + (ks & 1) * BUF;
        const uint32_t* sAh = base;
        const uint32_t* sAl = base + A_SZ;
        const uint32_t* sBh = base + 2 * A_SZ;
        const uint32_t* sBl = base + 2 * A_SZ + B_SZ;

#pragma unroll
        for (int ka = 0; ka < 2; ka++) {
            uint32_t bh[4][2], bl[4][2];
#pragma unroll
            for (int na = 0; na < 4; na++) {
                int n = wn * 32 + na * 8 + g;
                bh[na][0] = sBh[(ka * 8 + t) * 136 + n];
                bh[na][1] = sBh[(ka * 8 + t + 4) * 136 + n];
                bl[na][0] = sBl[(ka * 8 + t) * 136 + n];
                bl[na][1] = sBl[(ka * 8 + t + 4) * 136 + n];
            }
#pragma unroll
            for (int ma = 0; ma < 4; ma++) {
                int r = wm * 64 + ma * 16 + g;
                int c = ka * 8 + t;
                uint32_t ah0 = sAh[r * 20 + c],       ah1 = sAh[(r + 8) * 20 + c];
                uint32_t ah2 = sAh[r * 20 + c + 4],   ah3 = sAh[(r + 8) * 20 + c + 4];
                uint32_t al0 = sAl[r * 20 + c],       al1 = sAl[(r + 8) * 20 + c];
                uint32_t al2 = sAl[r * 20 + c + 4],   al3 = sAl[(r + 8) * 20 + c + 4];
#pragma unroll
                for (int na = 0; na < 4; na++) {
                    float* d = acc[ma][na];
                    bmma(d[0], d[1], d[2], d[3], ah0, ah1, ah2, ah3, bh[na][0], bh[na][1]);
                    bmma(d[0], d[1], d[2], d[3], ah0, ah1, ah2, ah3, bl[na][0], bl[na][1]);
                    bmma(d[0], d[1], d[2], d[3], al0, al1, al2, al3, bh[na][0], bh[na][1]);
                }
            }
        }

        if (ks + 1 < D / 32) store_smem((ks + 1) & 1);
        __syncthreads();
    }

#pragma unroll
    for (int ma = 0; ma < 4; ma++) {
#pragma unroll
        for (int na = 0; na < 4; na++) {
            int row = m0 + wm * 64 + ma * 16 + g;
            int col = n0 + wn * 32 + na * 8 + 2 * t;
            float b0 = bias[col], b1 = bias[col + 1];
            float* d = acc[ma][na];
            float v0 = d[0] + b0, v1 = d[1] + b1;
            float v2 = d[2] + b0, v3 = d[3] + b1;
            ushort2 hv, lv;
            splitone(v0, hv.x, lv.x);
            splitone(v1, hv.y, lv.y);
            *reinterpret_cast<ushort2*>(&oh[(size_t)row * D + col]) = hv;
            *reinterpret_cast<ushort2*>(&ol[(size_t)row * D + col]) = lv;
            splitone(v2, hv.x, lv.x);
            splitone(v3, hv.y, lv.y);
            *reinterpret_cast<ushort2*>(&oh[(size_t)(row + 8) * D + col]) = hv;
            *reinterpret_cast<ushort2*>(&ol[(size_t)(row + 8) * D + col]) = lv;
        }
    }
}

// ---------------------------------------------------------------------------
// Kernel 2: scores = Q Kt / 8 - 10000*(1-mask) + sumexp partials.
// Full K=64 in smem at once: ONE sync, then 192 MMAs with no barriers.
// (R10 version — legacy HMMA; tcgen05 is unavailable at compute_103.)
// ---------------------------------------------------------------------------
namespace sdims {
constexpr int ARR = 128 * 36;                 // u32 per array
constexpr int SMEM_BYTES = 4 * ARR * 4 + 128 * 4 * 4;   // 73728 + 2048
}

__global__ __launch_bounds__(256) void scores_kernel(
    const float* __restrict__ mask, float* __restrict__ out_s)
{
    using namespace cfg;
    using namespace sdims;
    const int bh = blockIdx.z;
    const int b  = bh >> 4, hd = bh & 15;
    const int q0 = blockIdx.y * 128;
    const int k0 = blockIdx.x * 128;

    extern __shared__ __align__(16) uint32_t dyn[];
    uint32_t* sQh = dyn;
    uint32_t* sQl = dyn + ARR;
    uint32_t* sKh = dyn + 2 * ARR;
    uint32_t* sKl = dyn + 3 * ARR;
    float* redS = reinterpret_cast<float*>(dyn + 4 * ARR);   // [128][4]

    const int tid = threadIdx.x;
    const int lane = tid & 31, wid = tid >> 5;
    const int g = lane >> 2, t = lane & 3;
    const int wm = wid & 1, wn = wid >> 1;

    const __nv_bfloat16* gQh = g_Qh + (size_t)(b * S + q0) * D + hd * W;
    const __nv_bfloat16* gQl = g_Ql + (size_t)(b * S + q0) * D + hd * W;
    const __nv_bfloat16* gKh = g_Kh + (size_t)(b * S + k0) * D + hd * W;
    const __nv_bfloat16* gKl = g_Kl + (size_t)(b * S + k0) * D + hd * W;

    // Load all Q/K hi/lo tiles (full 64-wide) into smem. 4 uint4 per array.
    {
        const int row = tid >> 3, ch = tid & 7;
#pragma unroll
        for (int p = 0; p < 4; p++) {
            int r = row + 32 * p;
            size_t go = (size_t)r * D + ch * 8;
            *reinterpret_cast<uint4*>(&sQh[r * 36 + ch * 4]) =
                *reinterpret_cast<const uint4*>(&gQh[go]);
            *reinterpret_cast<uint4*>(&sQl[r * 36 + ch * 4]) =
                *reinterpret_cast<const uint4*>(&gQl[go]);
            *reinterpret_cast<uint4*>(&sKh[r * 36 + ch * 4]) =
                *reinterpret_cast<const uint4*>(&gKh[go]);
            *reinterpret_cast<uint4*>(&sKl[r * 36 + ch * 4]) =
                *reinterpret_cast<const uint4*>(&gKl[go]);
        }
    }
    __syncthreads();

    float acc[4][4][4] = {};

#pragma unroll
    for (int ka = 0; ka < 4; ka++) {
        uint32_t bh_[4][2], bl_[4][2];
#pragma unroll
        for (int na = 0; na < 4; na++) {
            int n = wn * 32 + na * 8 + g;
            bh_[na][0] = sKh[n * 36 + ka * 8 + t];
            bh_[na][1] = sKh[n * 36 + ka * 8 + t + 4];
            bl_[na][0] = sKl[n * 36 + ka * 8 + t];
            bl_[na][1] = sKl[n * 36 + ka * 8 + t + 4];
        }
#pragma unroll
        for (int ma = 0; ma < 4; ma++) {
            int r = wm * 64 + ma * 16 + g;
            int c = ka * 8 + t;
            uint32_t ah0 = sQh[r * 36 + c],       ah1 = sQh[(r + 8) * 36 + c];
            uint32_t ah2 = sQh[r * 36 + c + 4],   ah3 = sQh[(r + 8) * 36 + c + 4];
            uint32_t al0 = sQl[r * 36 + c],       al1 = sQl[(r + 8) * 36 + c];
            uint32_t al2 = sQl[r * 36 + c + 4],   al3 = sQl[(r + 8) * 36 + c + 4];
#pragma unroll
            for (int na = 0; na < 4; na++) {
                float* d = acc[ma][na];
                bmma(d[0], d[1], d[2], d[3], ah0, ah1, ah2, ah3, bh_[na][0], bh_[na][1]);
                bmma(d[0], d[1], d[2], d[3], ah0, ah1, ah2, ah3, bl_[na][0], bl_[na][1]);
                bmma(d[0], d[1], d[2], d[3], al0, al1, al2, al3, bh_[na][0], bh_[na][1]);
            }
        }
    }

    // Scale + mask, store scores, accumulate sumexp partials (no max).
    const float scale = 0.125f;
    float* dst = out_s + ((size_t)bh * S + q0) * S + k0;
    float se[4][2] = {};

#pragma unroll
    for (int ma = 0; ma < 4; ma++) {
#pragma unroll
        for (int na = 0; na < 4; na++) {
            int rowl = wm * 64 + ma * 16 + g;
            int coll = wn * 32 + na * 8 + 2 * t;
            float m0v = mask[b * S + k0 + coll];
            float m1v = mask[b * S + k0 + coll + 1];
            float a0 = -10000.0f * (1.0f - m0v);
            float a1 = -10000.0f * (1.0f - m1v);
            float* d = acc[ma][na];
            float v0 = d[0] * scale + a0, v1 = d[1] * scale + a1;
            float v2 = d[2] * scale + a0, v3 = d[3] * scale + a1;
            *reinterpret_cast<float2*>(&dst[(size_t)rowl * S + coll]) = make_float2(v0, v1);
            *reinterpret_cast<float2*>(&dst[(size_t)(rowl + 8) * S + coll]) = make_float2(v2, v3);
            se[ma][0] += __expf(v0) + __expf(v1);
            se[ma][1] += __expf(v2) + __expf(v3);
        }
    }
#pragma unroll
    for (int ma = 0; ma < 4; ma++)
#pragma unroll
        for (int hf = 0; hf < 2; hf++) {
            float s = se[ma][hf];
            s += __shfl_xor_sync(0xffffffffu, s, 1);
            s += __shfl_xor_sync(0xffffffffu, s, 2);
            se[ma][hf] = s;
        }
    if (t == 0) {
#pragma unroll
        for (int ma = 0; ma < 4; ma++)
#pragma unroll
            for (int hf = 0; hf < 2; hf++)
                redS[(wm * 64 + ma * 16 + g + hf * 8) * 4 + wn] = se[ma][hf];
    }
    __syncthreads();

    if (tid < 128) {
        float s = redS[tid * 4 + 0] + redS[tid * 4 + 1]
                + redS[tid * 4 + 2] + redS[tid * 4 + 3];
        g_part[((size_t)bh * S + q0 + tid) * KT + blockIdx.x] = s;
    }
}

// ---------------------------------------------------------------------------
// Kernel 3: fused combine + softmax-apply + P@V, 3-term split-bf16.
// Prologue: threads 0-127 read their row's 16 sumexp partials -> 1/sum.
// Tile 128(q) x 64(w), BK=32, reg-prefetch.
// ---------------------------------------------------------------------------
__global__ __launch_bounds__(256, 2) void pv_kernel(
    const float* __restrict__ scores, float* __restrict__ soft,
    float* __restrict__ out_h)
{
    using namespace cfg;
    const int bh = blockIdx.y;
    const int b  = bh >> 4, hd = bh & 15;
    const int q0 = blockIdx.x * 128;

    __shared__ __align__(16) uint32_t sPh[128][20], sPl[128][20];
    __shared__ __align__(16) uint32_t sVh[16][72],  sVl[16][72];   // [k2][w]
    __shared__ float sInv[128];

    const int tid = threadIdx.x;
    const int lane = tid & 31, wid = tid >> 5;
    const int g = lane >> 2, t = lane & 3;
    const int wm = wid & 3, wn = wid >> 2;

    const float* Pbase = scores + ((size_t)bh * S + q0) * S;
    float* Sbase = soft + ((size_t)bh * S + q0) * S;
    const size_t vpair0 = (size_t)(b * S) / 2;

    // Fused combine: per-row 1/sum from the 16 tile partials (L2-resident).
    if (tid < 128) {
        const float* p = &g_part[((size_t)bh * S + q0 + tid) * KT];
        float4 a0 = *reinterpret_cast<const float4*>(&p[0]);
        float4 a1 = *reinterpret_cast<const float4*>(&p[4]);
        float4 a2 = *reinterpret_cast<const float4*>(&p[8]);
        float4 a3 = *reinterpret_cast<const float4*>(&p[12]);
        float s = (a0.x + a0.y + a0.z + a0.w) + (a1.x + a1.y + a1.z + a1.w)
                + (a2.x + a2.y + a2.z + a2.w) + (a3.x + a3.y + a3.z + a3.w);
        sInv[tid] = 1.0f / s;
    }
    __syncthreads();

    float acc[2][4][4] = {};
    float4 pr[4];
    uint4 rv[2];

    auto load_v = [&](int k0) {
#pragma unroll
        for (int p = 0; p < 2; p++) {
            int idx = tid & 255;
            int k2 = idx >> 4, ch = idx & 15;
            const uint32_t* src = p ? g_Vpl : g_Vph;
            rv[p] = *reinterpret_cast<const uint4*>(
                &src[(vpair0 + (k0 >> 1) + k2) * D + hd * W + ch * 4]);
        }
    };
    auto load_p = [&](int k0) {
#pragma unroll
        for (int p = 0; p < 4; p++) {
            int idx = tid + 256 * p;
            int row = idx >> 3;
            int c4  = (idx & 7) * 4;
            pr[p] = *reinterpret_cast<const float4*>(&Pbase[(size_t)row * S + k0 + c4]);
        }
    };

    load_p(0);
    load_v(0);

    for (int k0 = 0; k0 < S; k0 += 32) {
        // exp + write soft + split into smem
#pragma unroll
        for (int p = 0; p < 4; p++) {
            int idx = tid + 256 * p;
            int row = idx >> 3;
            int c4  = (idx & 7) * 4;
            float inv = sInv[row];
            float e0 = __expf(pr[p].x) * inv;
            float e1 = __expf(pr[p].y) * inv;
            float e2 = __expf(pr[p].z) * inv;
            float e3 = __expf(pr[p].w) * inv;
            *reinterpret_cast<float4*>(&Sbase[(size_t)row * S + k0 + c4]) =
                make_float4(e0, e1, e2, e3);
            uint32_t h0, l0, h1, l1;
            splitpair(e0, e1, h0, l0);
            splitpair(e2, e3, h1, l1);
            *reinterpret_cast<uint2*>(&sPh[row][c4 >> 1]) = make_uint2(h0, h1);
            *reinterpret_cast<uint2*>(&sPl[row][c4 >> 1]) = make_uint2(l0, l1);
        }
        {
            int idx = tid & 255;
            int k2 = idx >> 4, ch = idx & 15;
            *reinterpret_cast<uint4*>(&sVh[k2][ch * 4]) = rv[0];
            *reinterpret_cast<uint4*>(&sVl[k2][ch * 4]) = rv[1];
        }
        __syncthreads();

        if (k0 + 32 < S) {
            load_p(k0 + 32);
            load_v(k0 + 32);
        }

#pragma unroll
        for (int ka = 0; ka < 2; ka++) {
            uint32_t bh_[4][2], bl_[4][2];
#pragma unroll
            for (int na = 0; na < 4; na++) {
                int n = wn * 32 + na * 8 + g;
                bh_[na][0] = sVh[ka * 8 + t][n];
                bh_[na][1] = sVh[ka * 8 + t + 4][n];
                bl_[na][0] = sVl[ka * 8 + t][n];
                bl_[na][1] = sVl[ka * 8 + t + 4][n];
            }
#pragma unroll
            for (int ma = 0; ma < 2; ma++) {
                int r = wm * 32 + ma * 16 + g;
                int c = ka * 8 + t;
                uint32_t ah0 = sPh[r][c],     ah1 = sPh[r + 8][c];
                uint32_t ah2 = sPh[r][c + 4], ah3 = sPh[r + 8][c + 4];
                uint32_t al0 = sPl[r][c],     al1 = sPl[r + 8][c];
                uint32_t al2 = sPl[r][c + 4], al3 = sPl[r + 8][c + 4];
#pragma unroll
                for (int na = 0; na < 4; na++) {
                    float* d = acc[ma][na];
                    bmma(d[0], d[1], d[2], d[3], ah0, ah1, ah2, ah3, bh_[na][0], bh_[na][1]);
                    bmma(d[0], d[1], d[2], d[3], ah0, ah1, ah2, ah3, bl_[na][0], bl_[na][1]);
                    bmma(d[0], d[1], d[2], d[3], al0, al1, al2, al3, bh_[na][0], bh_[na][1]);
                }
            }
        }
        __syncthreads();
    }

#pragma unroll
    for (int ma = 0; ma < 2; ma++) {
#pragma unroll
        for (int na = 0; na < 4; na++) {
            int rowl = wm * 32 + ma * 16 + g;
            int coll = wn * 32 + na * 8 + 2 * t;
            float* d = acc[ma][na];
            size_t base = (size_t)(b * S + q0 + rowl) * D + hd * W + coll;
            *reinterpret_cast<float2*>(&out_h[base]) = make_float2(d[0], d[1]);
            *reinterpret_cast<float2*>(&out_h[base + (size_t)8 * D]) = make_float2(d[2], d[3]);
        }
    }
}

// ---------------------------------------------------------------------------
// Launch. d_out layout: [h | scores_soft | scores], fp32.
// ---------------------------------------------------------------------------
extern "C" void kernel_launch(void* const* d_in, const int* in_sizes, int n_in,
                              void* d_out, int out_size)
{
    using namespace cfg;
    (void)in_sizes; (void)n_in; (void)out_size;
    const float* x    = (const float*)d_in[0];
    const float* mask = (const float*)d_in[1];
    const float* wq   = (const float*)d_in[2];
    const float* bq   = (const float*)d_in[3];
    const float* wk   = (const float*)d_in[4];
    const float* bk   = (const float*)d_in[5];
    const float* wv   = (const float*)d_in[6];
    const float* bv   = (const float*)d_in[7];

    float* out   = (float*)d_out;
    float* out_h = out;
    float* out_p = out + H_ELEMS;              // scores_soft
    float* out_s = out + H_ELEMS + P_ELEMS;    // raw scores

    cudaFuncSetAttribute(qkv_gemm_kernel,
                         cudaFuncAttributeMaxDynamicSharedMemorySize,
                         qdims::SMEM_BYTES);
    cudaFuncSetAttribute(scores_kernel,
                         cudaFuncAttributeMaxDynamicSharedMemorySize,
                         sdims::SMEM_BYTES);

    split_x_kernel<<<M * D / 4 / 256, 256>>>(x);
    {
        dim3 grid((D / 2) * D / 256, 1, 3);
        pack_w_kernel<<<grid, 256>>>(wq, wk, wv);
    }
    {
        dim3 grid(D / 128, M / 128, 3);
        qkv_gemm_kernel<<<grid, 256, qdims::SMEM_BYTES>>>(bq, bk, bv);
    }
    repack_v_kernel<<<(M / 2) * (D / 2) / 256, 256>>>();
    {
        dim3 grid(S / 128, S / 128, B * H);
        scores_kernel<<<grid, 256, sdims::SMEM_BYTES>>>(mask, out_s);
    }
    {
        dim3 grid(S / 128, B * H);
        pv_kernel<<<grid, 256>>>(out_s, out_p, out_h);
    }
}